// round 14
// baseline (speedup 1.0000x reference)
#include <cuda_runtime.h>
#include <math.h>

#define NPTS_MAX 16384
#define KNBR 5
#define EPSV 1e-5f
#define GRID 16
#define NCELL (GRID * GRID * GRID)
#define CELLH 0.0625f

#define FMUL __fmul_rn
#define FADD __fadd_rn
#define FSUB __fsub_rn
#define FDIV __fdiv_rn
#define FMAF __fmaf_rn
#define FSQRT __fsqrt_rn

__device__ float4 g_pts4[NPTS_MAX];
__device__ int    g_cnt[NCELL];
__device__ int    g_off[NCELL];
__device__ int    g_ptr[NCELL];
__device__ int    g_cell[NPTS_MAX];
__device__ float4 g_sorted[NPTS_MAX];
__device__ int    g_sidx[NPTS_MAX];

// ---------------------------------------------------------------------------
// LAPACK fp32 helpers (netlib + gfortran -O2 contraction shapes) — FROZEN
// ---------------------------------------------------------------------------

__device__ __forceinline__ float f_sign(float a, float b) {
    return copysignf(fabsf(a), b);
}

__device__ __forceinline__ float slapy2f(float x, float y) {
    float xa = fabsf(x), ya = fabsf(y);
    float w = fmaxf(xa, ya), zz = fminf(xa, ya);
    if (zz == 0.0f) return w;
    float t = FDIV(zz, w);
    return FMUL(w, FSQRT(FMAF(t, t, 1.0f)));
}

__device__ void slartgf(float f, float g, float* c, float* s, float* r) {
    const float safmin = 1.17549435e-38f;
    const float safmax = 8.50705917e37f;
    const float rtmin  = 1.08420217e-19f;
    const float rtmax  = 6.52252447e18f;
    if (g == 0.0f) {
        *c = 1.0f; *s = 0.0f; *r = f;
    } else if (f == 0.0f) {
        *c = 0.0f;
        *s = (g >= 0.0f) ? 1.0f : -1.0f;
        *r = fabsf(g);
    } else {
        float f1 = fabsf(f), g1 = fabsf(g);
        if (f1 > rtmin && f1 < rtmax && g1 > rtmin && g1 < rtmax) {
            float d = FSQRT(FMAF(f, f, FMUL(g, g)));
            *c = FDIV(f1, d);
            *r = f_sign(d, f);
            *s = FDIV(g, *r);
        } else {
            float u = fminf(safmax, fmaxf(safmin, fmaxf(f1, g1)));
            float fs = FDIV(f, u), gs = FDIV(g, u);
            float d = FSQRT(FMAF(fs, fs, FMUL(gs, gs)));
            *c = FDIV(fabsf(fs), d);
            *r = f_sign(d, f);
            *s = FDIV(gs, *r);
            *r = FMUL(*r, u);
        }
    }
}

__device__ void slaev2f(float a, float b, float c_, float* rt1, float* rt2,
                        float* cs1, float* sn1) {
    float sm = FADD(a, c_);
    float df = FSUB(a, c_);
    float adf = fabsf(df);
    float tb = FADD(b, b);
    float ab = fabsf(tb);
    float acmx, acmn;
    if (fabsf(a) > fabsf(c_)) { acmx = a; acmn = c_; } else { acmx = c_; acmn = a; }
    float rt;
    if (adf > ab) {
        float t = FDIV(ab, adf);
        rt = FMUL(adf, FSQRT(FMAF(t, t, 1.0f)));
    } else if (adf < ab) {
        float t = FDIV(adf, ab);
        rt = FMUL(ab, FSQRT(FMAF(t, t, 1.0f)));
    } else {
        rt = FMUL(ab, 1.41421356f);
    }
    int sgn1;
    if (sm < 0.0f) {
        *rt1 = FMUL(0.5f, FSUB(sm, rt)); sgn1 = -1;
        float q1 = FDIV(acmx, *rt1), q2 = FDIV(b, *rt1);
        *rt2 = FMAF(q1, acmn, -FMUL(q2, b));
    } else if (sm > 0.0f) {
        *rt1 = FMUL(0.5f, FADD(sm, rt)); sgn1 = 1;
        float q1 = FDIV(acmx, *rt1), q2 = FDIV(b, *rt1);
        *rt2 = FMAF(q1, acmn, -FMUL(q2, b));
    } else {
        *rt1 = FMUL(0.5f, rt); *rt2 = FMUL(-0.5f, rt); sgn1 = 1;
    }
    float cs; int sgn2;
    if (df >= 0.0f) { cs = FADD(df, rt); sgn2 = 1; }
    else            { cs = FSUB(df, rt); sgn2 = -1; }
    float acs = fabsf(cs);
    if (acs > ab) {
        float ct = FDIV(-tb, cs);
        *sn1 = FDIV(1.0f, FSQRT(FMAF(ct, ct, 1.0f)));
        *cs1 = FMUL(ct, *sn1);
    } else {
        if (ab == 0.0f) { *cs1 = 1.0f; *sn1 = 0.0f; }
        else {
            float tn = FDIV(-cs, tb);
            *cs1 = FDIV(1.0f, FSQRT(FMAF(tn, tn, 1.0f)));
            *sn1 = FMUL(tn, *cs1);
        }
    }
    if (sgn1 == sgn2) {
        float tn = *cs1;
        *cs1 = -(*sn1);
        *sn1 = tn;
    }
}

// SSTEQR compz='I', n=3. z[i][j] = row i, col j (col j = eigenvector j).
__device__ void steqr3(float d[3], float e[2], float z[3][3]) {
    const int   n      = 3;
    const float eps    = 5.96046448e-08f;
    const float eps2   = 3.55271368e-15f;
    const float safmin = 1.17549435e-38f;
    const float ssfmax = 3.07445735e18f;
    const float ssfmin = 3.05175781e-05f;
    const int   nmaxit = 90;

    float wc[2], ws[2];
    int   jtot = 0, l1 = 1;
    int   l, lsv, lend, lendsv, m, mm, i, ii, j, k, iscale;
    float anorm = 0.0f, p, g, r, c, s, f, b, rt1, rt2, tst, mul, t;

L10:
    if (l1 > n) goto L160;
    if (l1 > 1) e[l1 - 2] = 0.0f;
    if (l1 <= n - 1) {
        for (m = l1; m <= n - 1; m++) {
            tst = fabsf(e[m - 1]);
            if (tst == 0.0f) goto L30;
            {
                float thr = FMUL(FMUL(FSQRT(fabsf(d[m - 1])), FSQRT(fabsf(d[m]))), eps);
                if (tst <= thr) { e[m - 1] = 0.0f; goto L30; }
            }
        }
    }
    m = n;
L30:
    l = l1; lsv = l; lend = m; lendsv = lend; l1 = m + 1;
    if (lend == l) goto L10;

    anorm = fabsf(d[lend - 1]);
    for (i = l; i <= lend - 1; i++) {
        anorm = fmaxf(anorm, fabsf(d[i - 1]));
        anorm = fmaxf(anorm, fabsf(e[i - 1]));
    }
    iscale = 0;
    if (anorm == 0.0f) goto L10;
    if (anorm > ssfmax) {
        iscale = 1; mul = FDIV(ssfmax, anorm);
        for (i = l; i <= lend; i++) d[i - 1] = FMUL(d[i - 1], mul);
        for (i = l; i <= lend - 1; i++) e[i - 1] = FMUL(e[i - 1], mul);
    } else if (anorm < ssfmin) {
        iscale = 2; mul = FDIV(ssfmin, anorm);
        for (i = l; i <= lend; i++) d[i - 1] = FMUL(d[i - 1], mul);
        for (i = l; i <= lend - 1; i++) e[i - 1] = FMUL(e[i - 1], mul);
    }

    if (fabsf(d[lend - 1]) < fabsf(d[l - 1])) { lend = lsv; l = lendsv; }

    if (lend > l) {
L40:
        if (l != lend) {
            for (m = l; m <= lend - 1; m++) {
                tst = FMUL(e[m - 1], e[m - 1]);
                float rhs = FMAF(FMUL(eps2, fabsf(d[m - 1])), fabsf(d[m]), safmin);
                if (tst <= rhs) goto L60;
            }
        }
        m = lend;
L60:
        if (m < lend) e[m - 1] = 0.0f;
        p = d[l - 1];
        if (m == l) goto L80;
        if (m == l + 1) {
            slaev2f(d[l - 1], e[l - 1], d[l], &rt1, &rt2, &c, &s);
            for (i = 0; i < 3; i++) {
                t = z[i][l];
                z[i][l]     = FMAF(c, t, -FMUL(s, z[i][l - 1]));
                z[i][l - 1] = FMAF(s, t,  FMUL(c, z[i][l - 1]));
            }
            d[l - 1] = rt1; d[l] = rt2; e[l - 1] = 0.0f;
            l += 2;
            if (l <= lend) goto L40;
            goto L140;
        }
        if (jtot == nmaxit) goto L140;
        jtot++;
        g = FDIV(FSUB(d[l], p), FMUL(2.0f, e[l - 1]));
        r = slapy2f(g, 1.0f);
        g = FADD(FSUB(d[m - 1], p), FDIV(e[l - 1], FADD(g, f_sign(r, g))));
        s = 1.0f; c = 1.0f; p = 0.0f;
        for (i = m - 1; i >= l; i--) {
            f = FMUL(s, e[i - 1]); b = FMUL(c, e[i - 1]);
            slartgf(g, f, &c, &s, &r);
            if (i != m - 1) e[i] = r;
            g = FSUB(d[i], p);
            r = FMAF(FSUB(d[i - 1], g), s, FMUL(FMUL(2.0f, c), b));
            p = FMUL(s, r);
            d[i] = FADD(g, p);
            g = FMAF(c, r, -b);
            wc[i - l] = c;
            ws[i - l] = -s;
        }
        mm = m - l + 1;
        for (j = mm - 1; j >= 1; j--) {
            float cj = wc[j - 1], sj = ws[j - 1];
            for (i = 0; i < 3; i++) {
                t = z[i][l + j - 1];
                z[i][l + j - 1] = FMAF(cj, t, -FMUL(sj, z[i][l + j - 2]));
                z[i][l + j - 2] = FMAF(sj, t,  FMUL(cj, z[i][l + j - 2]));
            }
        }
        d[l - 1] = FSUB(d[l - 1], p);
        e[l - 1] = g;
        goto L40;
L80:
        d[l - 1] = p; l++;
        if (l <= lend) goto L40;
        goto L140;
    } else {
L90:
        if (l != lend) {
            for (m = l; m >= lend + 1; m--) {
                tst = FMUL(e[m - 2], e[m - 2]);
                float rhs = FMAF(FMUL(eps2, fabsf(d[m - 1])), fabsf(d[m - 2]), safmin);
                if (tst <= rhs) goto L110;
            }
        }
        m = lend;
L110:
        if (m > lend) e[m - 2] = 0.0f;
        p = d[l - 1];
        if (m == l) goto L130;
        if (m == l - 1) {
            slaev2f(d[l - 2], e[l - 2], d[l - 1], &rt1, &rt2, &c, &s);
            for (i = 0; i < 3; i++) {
                t = z[i][l - 1];
                z[i][l - 1] = FMAF(c, t, -FMUL(s, z[i][l - 2]));
                z[i][l - 2] = FMAF(s, t,  FMUL(c, z[i][l - 2]));
            }
            d[l - 2] = rt1; d[l - 1] = rt2; e[l - 2] = 0.0f;
            l -= 2;
            if (l >= lend) goto L90;
            goto L140;
        }
        if (jtot == nmaxit) goto L140;
        jtot++;
        g = FDIV(FSUB(d[l - 2], p), FMUL(2.0f, e[l - 2]));
        r = slapy2f(g, 1.0f);
        g = FADD(FSUB(d[m - 1], p), FDIV(e[l - 2], FADD(g, f_sign(r, g))));
        s = 1.0f; c = 1.0f; p = 0.0f;
        for (i = m; i <= l - 1; i++) {
            f = FMUL(s, e[i - 1]); b = FMUL(c, e[i - 1]);
            slartgf(g, f, &c, &s, &r);
            if (i != m) e[i - 2] = r;
            g = FSUB(d[i - 1], p);
            r = FMAF(FSUB(d[i], g), s, FMUL(FMUL(2.0f, c), b));
            p = FMUL(s, r);
            d[i - 1] = FADD(g, p);
            g = FMAF(c, r, -b);
            wc[i - m] = c;
            ws[i - m] = s;
        }
        mm = l - m + 1;
        for (j = 1; j <= mm - 1; j++) {
            float cj = wc[j - 1], sj = ws[j - 1];
            for (i = 0; i < 3; i++) {
                t = z[i][m + j - 1];
                z[i][m + j - 1] = FMAF(cj, t, -FMUL(sj, z[i][m + j - 2]));
                z[i][m + j - 2] = FMAF(sj, t,  FMUL(cj, z[i][m + j - 2]));
            }
        }
        d[l - 1] = FSUB(d[l - 1], p);
        e[l - 2] = g;
        goto L90;
L130:
        d[l - 1] = p; l--;
        if (l >= lend) goto L90;
        goto L140;
    }
L140:
    if (iscale == 1) {
        mul = FDIV(anorm, ssfmax);
        for (i = lsv; i <= lendsv; i++) d[i - 1] = FMUL(d[i - 1], mul);
        for (i = lsv; i <= lendsv - 1; i++) e[i - 1] = FMUL(e[i - 1], mul);
    } else if (iscale == 2) {
        mul = FDIV(anorm, ssfmin);
        for (i = lsv; i <= lendsv; i++) d[i - 1] = FMUL(d[i - 1], mul);
        for (i = lsv; i <= lendsv - 1; i++) e[i - 1] = FMUL(e[i - 1], mul);
    }
    if (jtot < nmaxit) goto L10;
    goto L190;
L160:
    for (ii = 2; ii <= n; ii++) {
        i = ii - 1; k = i; p = d[i - 1];
        for (j = ii; j <= n; j++) {
            if (d[j - 1] < p) { k = j; p = d[j - 1]; }
        }
        if (k != i) {
            d[k - 1] = d[i - 1]; d[i - 1] = p;
            for (int rr = 0; rr < 3; rr++) {
                t = z[rr][i - 1]; z[rr][i - 1] = z[rr][k - 1]; z[rr][k - 1] = t;
            }
        }
    }
L190:
    return;
}

// ---------------------------------------------------------------------------
// Kernel 1: pack (x,y,z,||p||^2) STRICT + cell id + count
// ---------------------------------------------------------------------------
__global__ void pack_kernel(const float* __restrict__ pts, int n) {
    int i = blockIdx.x * blockDim.x + threadIdx.x;
    if (i < n) {
        float x = pts[3 * i + 0];
        float y = pts[3 * i + 1];
        float z = pts[3 * i + 2];
        float sq = FADD(FADD(FMUL(x, x), FMUL(y, y)), FMUL(z, z));
        g_pts4[i] = make_float4(x, y, z, sq);
        int cx = min(GRID - 1, max(0, (int)(x * (float)GRID)));
        int cy = min(GRID - 1, max(0, (int)(y * (float)GRID)));
        int cz = min(GRID - 1, max(0, (int)(z * (float)GRID)));
        int cid = (cz * GRID + cy) * GRID + cx;
        g_cell[i] = cid;
        atomicAdd(&g_cnt[cid], 1);
    }
}

// ---------------------------------------------------------------------------
// Kernel 2: exclusive scan of 4096 cell counts (single block, 1024 threads)
// ---------------------------------------------------------------------------
__global__ void scan_kernel() {
    __shared__ int sh[1024];
    int t = threadIdx.x;
    int c0 = g_cnt[4 * t + 0];
    int c1 = g_cnt[4 * t + 1];
    int c2 = g_cnt[4 * t + 2];
    int c3 = g_cnt[4 * t + 3];
    int sum = c0 + c1 + c2 + c3;
    sh[t] = sum;
    __syncthreads();
    for (int off = 1; off < 1024; off <<= 1) {
        int v = (t >= off) ? sh[t - off] : 0;
        __syncthreads();
        sh[t] += v;
        __syncthreads();
    }
    int excl = sh[t] - sum;
    g_off[4 * t + 0] = excl;
    g_off[4 * t + 1] = excl + c0;
    g_off[4 * t + 2] = excl + c0 + c1;
    g_off[4 * t + 3] = excl + c0 + c1 + c2;
    g_ptr[4 * t + 0] = excl;
    g_ptr[4 * t + 1] = excl + c0;
    g_ptr[4 * t + 2] = excl + c0 + c1;
    g_ptr[4 * t + 3] = excl + c0 + c1 + c2;
}

// ---------------------------------------------------------------------------
// Kernel 3: scatter points into cell-sorted order
// ---------------------------------------------------------------------------
__global__ void scatter_kernel(int n) {
    int i = blockIdx.x * blockDim.x + threadIdx.x;
    if (i < n) {
        int c = g_cell[i];
        int pos = atomicAdd(&g_ptr[c], 1);
        g_sorted[pos] = g_pts4[i];
        g_sidx[pos] = i;
    }
}

// ---------------------------------------------------------------------------
// Kernel 4 (FUSED): grid 5-NN (stable (d2,idx) top-k, expanding rings) + LRF.
// Queries in cell-sorted order. 64-thread blocks -> 256 CTAs cover all SMs.
// ---------------------------------------------------------------------------
__global__ void knn_lrf_kernel(float* __restrict__ out, int n) {
    int s = blockIdx.x * blockDim.x + threadIdx.x;
    if (s >= n) return;
    float4 q = g_sorted[s];
    int qi = g_sidx[s];

    int cx = min(GRID - 1, max(0, (int)(q.x * (float)GRID)));
    int cy = min(GRID - 1, max(0, (int)(q.y * (float)GRID)));
    int cz = min(GRID - 1, max(0, (int)(q.z * (float)GRID)));

    float bd0 = INFINITY, bd1 = INFINITY, bd2 = INFINITY, bd3 = INFINITY, bd4 = INFINITY;
    int   bi0 = 0x7FFFFFFF, bi1 = 0x7FFFFFFF, bi2 = 0x7FFFFFFF, bi3 = 0x7FFFFFFF, bi4 = 0x7FFFFFFF;

#define KNN_CAND(PVEC, PIDX)                                                    \
    do {                                                                        \
        float4 p = (PVEC);                                                      \
        int idx = (PIDX);                                                       \
        float dot = FADD(FADD(FMUL(q.x, p.x), FMUL(q.y, p.y)), FMUL(q.z, p.z)); \
        float d2 = FSUB(FADD(q.w, p.w), FMUL(2.0f, dot));                       \
        if (d2 < bd4 || (d2 == bd4 && idx < bi4)) {                             \
            if (d2 < bd3 || (d2 == bd3 && idx < bi3)) {                         \
                bd4 = bd3; bi4 = bi3;                                           \
                if (d2 < bd2 || (d2 == bd2 && idx < bi2)) {                     \
                    bd3 = bd2; bi3 = bi2;                                       \
                    if (d2 < bd1 || (d2 == bd1 && idx < bi1)) {                 \
                        bd2 = bd1; bi2 = bi1;                                   \
                        if (d2 < bd0 || (d2 == bd0 && idx < bi0)) {             \
                            bd1 = bd0; bi1 = bi0;                               \
                            bd0 = d2; bi0 = idx;                                \
                        } else { bd1 = d2; bi1 = idx; }                         \
                    } else { bd2 = d2; bi2 = idx; }                             \
                } else { bd3 = d2; bi3 = idx; }                                 \
            } else { bd4 = d2; bi4 = idx; }                                     \
        }                                                                       \
    } while (0)

    // ---- R = 1: clamped 3x3x3 block ----
    {
        int z0 = max(cz - 1, 0), z1 = min(cz + 1, GRID - 1);
        int y0 = max(cy - 1, 0), y1 = min(cy + 1, GRID - 1);
        int x0 = max(cx - 1, 0), x1 = min(cx + 1, GRID - 1);
        for (int zz = z0; zz <= z1; zz++)
            for (int yy = y0; yy <= y1; yy++) {
                int rowbase = (zz * GRID + yy) * GRID;
                for (int xx = x0; xx <= x1; xx++) {
                    int cid = rowbase + xx;
                    int a = g_off[cid];
                    int b = a + g_cnt[cid];
                    for (int t = a; t < b; t++) KNN_CAND(g_sorted[t], g_sidx[t]);
                }
            }
    }

    // ---- R >= 2 shells (rare) ----
    {
        float guard = CELLH;
        if (!(bd4 < guard * guard - 1e-5f)) {
            for (int R = 2; R <= GRID - 1; R++) {
                for (int dz = -R; dz <= R; dz++) {
                    int zz = cz + dz;
                    if (zz < 0 || zz >= GRID) continue;
                    for (int dy = -R; dy <= R; dy++) {
                        int yy = cy + dy;
                        if (yy < 0 || yy >= GRID) continue;
                        for (int dxc = -R; dxc <= R; dxc++) {
                            int xx = cx + dxc;
                            if (xx < 0 || xx >= GRID) continue;
                            int cheb = max(abs(dz), max(abs(dy), abs(dxc)));
                            if (cheb != R) continue;
                            int cid = (zz * GRID + yy) * GRID + xx;
                            int a = g_off[cid];
                            int b = a + g_cnt[cid];
                            for (int t = a; t < b; t++) KNN_CAND(g_sorted[t], g_sidx[t]);
                        }
                    }
                }
                float g2 = (float)R * CELLH;
                if (bd4 < g2 * g2 - 1e-5f) break;
            }
        }
    }
#undef KNN_CAND

    // =======================================================================
    // LRF (FROZEN bit recipe)
    // =======================================================================
    int nbr[KNBR] = { bi0, bi1, bi2, bi3, bi4 };
    float dx[KNBR], dy[KNBR], dz[KNBR];
    #pragma unroll
    for (int k = 0; k < KNBR; k++) {
        float4 p = g_pts4[nbr[k]];
        dx[k] = FSUB(p.x, q.x);
        dy[k] = FSUB(p.y, q.y);
        dz[k] = FSUB(p.z, q.z);
    }
    float sxm = FADD(FADD(FADD(FADD(dx[0], dx[1]), dx[2]), dx[3]), dx[4]);
    float sym = FADD(FADD(FADD(FADD(dy[0], dy[1]), dy[2]), dy[3]), dy[4]);
    float szm = FADD(FADD(FADD(FADD(dz[0], dz[1]), dz[2]), dz[3]), dz[4]);
    float mx = FDIV(sxm, 5.0f);
    float my = FDIV(sym, 5.0f);
    float mz = FDIV(szm, 5.0f);

    float cxa[KNBR], cya[KNBR], cza[KNBR];
    #pragma unroll
    for (int k = 0; k < KNBR; k++) {
        cxa[k] = FSUB(dx[k], mx);
        cya[k] = FSUB(dy[k], my);
        cza[k] = FSUB(dz[k], mz);
    }
    float c00 = 0.f, c10 = 0.f, c20 = 0.f, c11 = 0.f, c21 = 0.f, c22 = 0.f;
    #pragma unroll
    for (int k = 0; k < KNBR; k++) {
        c00 = FMAF(cxa[k], cxa[k], c00);
        c10 = FMAF(cya[k], cxa[k], c10);
        c20 = FMAF(cza[k], cxa[k], c20);
        c11 = FMAF(cya[k], cya[k], c11);
        c21 = FMAF(cza[k], cya[k], c21);
        c22 = FMAF(cza[k], cza[k], c22);
    }
    c00 = FDIV(c00, 5.0f); c10 = FDIV(c10, 5.0f); c20 = FDIV(c20, 5.0f);
    c11 = FDIV(c11, 5.0f); c21 = FDIV(c21, 5.0f); c22 = FDIV(c22, 5.0f);

    // ---- ssytd2 'L', n=3 ----
    float e0, e1s, tau = 0.0f, v2 = 0.0f;
    float a11 = c11, a21 = c21, a22 = c22;
    {
        float alpha = c10;
        float xnorm = FSQRT(FMUL(c20, c20));
        if (xnorm == 0.0f) {
            tau = 0.0f;
            e0 = alpha;
        } else {
            float beta = -f_sign(slapy2f(alpha, xnorm), alpha);
            tau = FDIV(FSUB(beta, alpha), beta);
            v2  = FMUL(c20, FDIV(1.0f, FSUB(alpha, beta)));
            e0  = beta;
            float y1 = FMAF(tau, FMUL(a21, v2), FMUL(tau, a11));
            float y2 = FMAF(FMUL(tau, v2), a22, FMUL(tau, a21));
            float sdot = FMAF(y2, v2, y1);
            float ac = FMUL(FMUL(-0.5f, tau), sdot);
            y1 = FMAF(ac, 1.0f, y1);
            y2 = FMAF(ac, v2, y2);
            a11 = FMAF(y1, -1.0f, FMAF(1.0f, -y1, a11));
            a21 = FMAF(y2, -1.0f, FMAF(v2,  -y1, a21));
            a22 = FMAF(y2, -v2,   FMAF(v2,  -y2, a22));
        }
        e1s = a21;
    }

    float d[3] = { c00, a11, a22 };
    float e[2] = { e0, e1s };
    float z[3][3] = { {1.f,0.f,0.f}, {0.f,1.f,0.f}, {0.f,0.f,1.f} };

    steqr3(d, e, z);

    if (tau != 0.0f) {
        #pragma unroll
        for (int jc = 0; jc < 3; jc++) {
            float w = FMAF(z[2][jc], v2, z[1][jc]);
            float tneg = FMUL(-tau, w);
            z[1][jc] = FMAF(1.0f, tneg, z[1][jc]);
            z[2][jc] = FMAF(v2,  tneg, z[2][jc]);
        }
    }

    float xr0 = z[2][0], xr1 = z[2][1], xr2 = z[2][2];
    float zr0 = z[0][0], zr1 = z[0][1], zr2 = z[0][2];

    int cx_cnt = 0, cz_cnt = 0;
    #pragma unroll
    for (int k = 0; k < KNBR; k++) {
        float wx = FSUB(dx[k], q.x);
        float wy = FSUB(dy[k], q.y);
        float wz = FSUB(dz[k], q.z);
        float dotx = FMAF(wz, xr2, FMAF(wy, xr1, FMUL(wx, xr0)));
        float dotz = FMAF(wz, zr2, FMAF(wy, zr1, FMUL(wx, zr0)));
        if (dotx >= -EPSV) cx_cnt++;
        if (dotz >= -EPSV) cz_cnt++;
    }
    float sx = (2 * cx_cnt >= KNBR) ? 1.0f : -1.0f;
    float sz = (2 * cz_cnt >= KNBR) ? 1.0f : -1.0f;

    float xa0 = FMUL(xr0, sx), xa1 = FMUL(xr1, sx), xa2 = FMUL(xr2, sx);
    float za0 = FMUL(zr0, sz), za1 = FMUL(zr1, sz), za2 = FMUL(zr2, sz);
    float ya0 = FSUB(FMUL(za1, xa2), FMUL(za2, xa1));
    float ya1 = FSUB(FMUL(za2, xa0), FMUL(za0, xa2));
    float ya2 = FSUB(FMUL(za0, xa1), FMUL(za1, xa0));

    float* o = out + (size_t)qi * 9;
    o[0] = xa0; o[1] = xa1; o[2] = xa2;
    o[3] = ya0; o[4] = ya1; o[5] = ya2;
    o[6] = za0; o[7] = za1; o[8] = za2;
}

// ---------------------------------------------------------------------------
extern "C" void kernel_launch(void* const* d_in, const int* in_sizes, int n_in,
                              void* d_out, int out_size) {
    const float* pts = (const float*)d_in[0];
    float* out = (float*)d_out;
    int n = in_sizes[0] / 3;
    if (n > NPTS_MAX) n = NPTS_MAX;

    void* cnt_ptr = nullptr;
    cudaGetSymbolAddress(&cnt_ptr, g_cnt);
    cudaMemsetAsync(cnt_ptr, 0, NCELL * sizeof(int));

    pack_kernel<<<(n + 255) / 256, 256>>>(pts, n);
    scan_kernel<<<1, 1024>>>();
    scatter_kernel<<<(n + 255) / 256, 256>>>(n);
    knn_lrf_kernel<<<(n + 63) / 64, 64>>>(out, n);
}

// round 15
// speedup vs baseline: 1.4388x; 1.4388x over previous
#include <cuda_runtime.h>
#include <math.h>

#define NPTS_MAX 16384
#define KNBR 5
#define EPSV 1e-5f
#define GRID 16
#define NCELL (GRID * GRID * GRID)
#define CELLH 0.0625f

#define FMUL __fmul_rn
#define FADD __fadd_rn
#define FSUB __fsub_rn
#define FDIV __fdiv_rn
#define FMAF __fmaf_rn
#define FSQRT __fsqrt_rn

__device__ float4 g_pts4[NPTS_MAX];
__device__ int    g_cnt[NCELL];
__device__ int    g_off[NCELL];
__device__ int    g_ptr[NCELL];
__device__ int    g_cell[NPTS_MAX];
__device__ float4 g_sorted[NPTS_MAX];
__device__ int    g_sidx[NPTS_MAX];

// ---------------------------------------------------------------------------
// LAPACK fp32 helpers (netlib + gfortran -O2 contraction shapes) — FROZEN
// ---------------------------------------------------------------------------

__device__ __forceinline__ float f_sign(float a, float b) {
    return copysignf(fabsf(a), b);
}

__device__ __forceinline__ float slapy2f(float x, float y) {
    float xa = fabsf(x), ya = fabsf(y);
    float w = fmaxf(xa, ya), zz = fminf(xa, ya);
    if (zz == 0.0f) return w;
    float t = FDIV(zz, w);
    return FMUL(w, FSQRT(FMAF(t, t, 1.0f)));
}

__device__ void slartgf(float f, float g, float* c, float* s, float* r) {
    const float safmin = 1.17549435e-38f;
    const float safmax = 8.50705917e37f;
    const float rtmin  = 1.08420217e-19f;
    const float rtmax  = 6.52252447e18f;
    if (g == 0.0f) {
        *c = 1.0f; *s = 0.0f; *r = f;
    } else if (f == 0.0f) {
        *c = 0.0f;
        *s = (g >= 0.0f) ? 1.0f : -1.0f;
        *r = fabsf(g);
    } else {
        float f1 = fabsf(f), g1 = fabsf(g);
        if (f1 > rtmin && f1 < rtmax && g1 > rtmin && g1 < rtmax) {
            float d = FSQRT(FMAF(f, f, FMUL(g, g)));
            *c = FDIV(f1, d);
            *r = f_sign(d, f);
            *s = FDIV(g, *r);
        } else {
            float u = fminf(safmax, fmaxf(safmin, fmaxf(f1, g1)));
            float fs = FDIV(f, u), gs = FDIV(g, u);
            float d = FSQRT(FMAF(fs, fs, FMUL(gs, gs)));
            *c = FDIV(fabsf(fs), d);
            *r = f_sign(d, f);
            *s = FDIV(gs, *r);
            *r = FMUL(*r, u);
        }
    }
}

__device__ void slaev2f(float a, float b, float c_, float* rt1, float* rt2,
                        float* cs1, float* sn1) {
    float sm = FADD(a, c_);
    float df = FSUB(a, c_);
    float adf = fabsf(df);
    float tb = FADD(b, b);
    float ab = fabsf(tb);
    float acmx, acmn;
    if (fabsf(a) > fabsf(c_)) { acmx = a; acmn = c_; } else { acmx = c_; acmn = a; }
    float rt;
    if (adf > ab) {
        float t = FDIV(ab, adf);
        rt = FMUL(adf, FSQRT(FMAF(t, t, 1.0f)));
    } else if (adf < ab) {
        float t = FDIV(adf, ab);
        rt = FMUL(ab, FSQRT(FMAF(t, t, 1.0f)));
    } else {
        rt = FMUL(ab, 1.41421356f);
    }
    int sgn1;
    if (sm < 0.0f) {
        *rt1 = FMUL(0.5f, FSUB(sm, rt)); sgn1 = -1;
        float q1 = FDIV(acmx, *rt1), q2 = FDIV(b, *rt1);
        *rt2 = FMAF(q1, acmn, -FMUL(q2, b));
    } else if (sm > 0.0f) {
        *rt1 = FMUL(0.5f, FADD(sm, rt)); sgn1 = 1;
        float q1 = FDIV(acmx, *rt1), q2 = FDIV(b, *rt1);
        *rt2 = FMAF(q1, acmn, -FMUL(q2, b));
    } else {
        *rt1 = FMUL(0.5f, rt); *rt2 = FMUL(-0.5f, rt); sgn1 = 1;
    }
    float cs; int sgn2;
    if (df >= 0.0f) { cs = FADD(df, rt); sgn2 = 1; }
    else            { cs = FSUB(df, rt); sgn2 = -1; }
    float acs = fabsf(cs);
    if (acs > ab) {
        float ct = FDIV(-tb, cs);
        *sn1 = FDIV(1.0f, FSQRT(FMAF(ct, ct, 1.0f)));
        *cs1 = FMUL(ct, *sn1);
    } else {
        if (ab == 0.0f) { *cs1 = 1.0f; *sn1 = 0.0f; }
        else {
            float tn = FDIV(-cs, tb);
            *cs1 = FDIV(1.0f, FSQRT(FMAF(tn, tn, 1.0f)));
            *sn1 = FMUL(tn, *cs1);
        }
    }
    if (sgn1 == sgn2) {
        float tn = *cs1;
        *cs1 = -(*sn1);
        *sn1 = tn;
    }
}

// SSTEQR compz='I', n=3.
__device__ void steqr3(float d[3], float e[2], float z[3][3]) {
    const int   n      = 3;
    const float eps    = 5.96046448e-08f;
    const float eps2   = 3.55271368e-15f;
    const float safmin = 1.17549435e-38f;
    const float ssfmax = 3.07445735e18f;
    const float ssfmin = 3.05175781e-05f;
    const int   nmaxit = 90;

    float wc[2], ws[2];
    int   jtot = 0, l1 = 1;
    int   l, lsv, lend, lendsv, m, mm, i, ii, j, k, iscale;
    float anorm = 0.0f, p, g, r, c, s, f, b, rt1, rt2, tst, mul, t;

L10:
    if (l1 > n) goto L160;
    if (l1 > 1) e[l1 - 2] = 0.0f;
    if (l1 <= n - 1) {
        for (m = l1; m <= n - 1; m++) {
            tst = fabsf(e[m - 1]);
            if (tst == 0.0f) goto L30;
            {
                float thr = FMUL(FMUL(FSQRT(fabsf(d[m - 1])), FSQRT(fabsf(d[m]))), eps);
                if (tst <= thr) { e[m - 1] = 0.0f; goto L30; }
            }
        }
    }
    m = n;
L30:
    l = l1; lsv = l; lend = m; lendsv = lend; l1 = m + 1;
    if (lend == l) goto L10;

    anorm = fabsf(d[lend - 1]);
    for (i = l; i <= lend - 1; i++) {
        anorm = fmaxf(anorm, fabsf(d[i - 1]));
        anorm = fmaxf(anorm, fabsf(e[i - 1]));
    }
    iscale = 0;
    if (anorm == 0.0f) goto L10;
    if (anorm > ssfmax) {
        iscale = 1; mul = FDIV(ssfmax, anorm);
        for (i = l; i <= lend; i++) d[i - 1] = FMUL(d[i - 1], mul);
        for (i = l; i <= lend - 1; i++) e[i - 1] = FMUL(e[i - 1], mul);
    } else if (anorm < ssfmin) {
        iscale = 2; mul = FDIV(ssfmin, anorm);
        for (i = l; i <= lend; i++) d[i - 1] = FMUL(d[i - 1], mul);
        for (i = l; i <= lend - 1; i++) e[i - 1] = FMUL(e[i - 1], mul);
    }

    if (fabsf(d[lend - 1]) < fabsf(d[l - 1])) { lend = lsv; l = lendsv; }

    if (lend > l) {
L40:
        if (l != lend) {
            for (m = l; m <= lend - 1; m++) {
                tst = FMUL(e[m - 1], e[m - 1]);
                float rhs = FMAF(FMUL(eps2, fabsf(d[m - 1])), fabsf(d[m]), safmin);
                if (tst <= rhs) goto L60;
            }
        }
        m = lend;
L60:
        if (m < lend) e[m - 1] = 0.0f;
        p = d[l - 1];
        if (m == l) goto L80;
        if (m == l + 1) {
            slaev2f(d[l - 1], e[l - 1], d[l], &rt1, &rt2, &c, &s);
            for (i = 0; i < 3; i++) {
                t = z[i][l];
                z[i][l]     = FMAF(c, t, -FMUL(s, z[i][l - 1]));
                z[i][l - 1] = FMAF(s, t,  FMUL(c, z[i][l - 1]));
            }
            d[l - 1] = rt1; d[l] = rt2; e[l - 1] = 0.0f;
            l += 2;
            if (l <= lend) goto L40;
            goto L140;
        }
        if (jtot == nmaxit) goto L140;
        jtot++;
        g = FDIV(FSUB(d[l], p), FMUL(2.0f, e[l - 1]));
        r = slapy2f(g, 1.0f);
        g = FADD(FSUB(d[m - 1], p), FDIV(e[l - 1], FADD(g, f_sign(r, g))));
        s = 1.0f; c = 1.0f; p = 0.0f;
        for (i = m - 1; i >= l; i--) {
            f = FMUL(s, e[i - 1]); b = FMUL(c, e[i - 1]);
            slartgf(g, f, &c, &s, &r);
            if (i != m - 1) e[i] = r;
            g = FSUB(d[i], p);
            r = FMAF(FSUB(d[i - 1], g), s, FMUL(FMUL(2.0f, c), b));
            p = FMUL(s, r);
            d[i] = FADD(g, p);
            g = FMAF(c, r, -b);
            wc[i - l] = c;
            ws[i - l] = -s;
        }
        mm = m - l + 1;
        for (j = mm - 1; j >= 1; j--) {
            float cj = wc[j - 1], sj = ws[j - 1];
            for (i = 0; i < 3; i++) {
                t = z[i][l + j - 1];
                z[i][l + j - 1] = FMAF(cj, t, -FMUL(sj, z[i][l + j - 2]));
                z[i][l + j - 2] = FMAF(sj, t,  FMUL(cj, z[i][l + j - 2]));
            }
        }
        d[l - 1] = FSUB(d[l - 1], p);
        e[l - 1] = g;
        goto L40;
L80:
        d[l - 1] = p; l++;
        if (l <= lend) goto L40;
        goto L140;
    } else {
L90:
        if (l != lend) {
            for (m = l; m >= lend + 1; m--) {
                tst = FMUL(e[m - 2], e[m - 2]);
                float rhs = FMAF(FMUL(eps2, fabsf(d[m - 1])), fabsf(d[m - 2]), safmin);
                if (tst <= rhs) goto L110;
            }
        }
        m = lend;
L110:
        if (m > lend) e[m - 2] = 0.0f;
        p = d[l - 1];
        if (m == l) goto L130;
        if (m == l - 1) {
            slaev2f(d[l - 2], e[l - 2], d[l - 1], &rt1, &rt2, &c, &s);
            for (i = 0; i < 3; i++) {
                t = z[i][l - 1];
                z[i][l - 1] = FMAF(c, t, -FMUL(s, z[i][l - 2]));
                z[i][l - 2] = FMAF(s, t,  FMUL(c, z[i][l - 2]));
            }
            d[l - 2] = rt1; d[l - 1] = rt2; e[l - 2] = 0.0f;
            l -= 2;
            if (l >= lend) goto L90;
            goto L140;
        }
        if (jtot == nmaxit) goto L140;
        jtot++;
        g = FDIV(FSUB(d[l - 2], p), FMUL(2.0f, e[l - 2]));
        r = slapy2f(g, 1.0f);
        g = FADD(FSUB(d[m - 1], p), FDIV(e[l - 2], FADD(g, f_sign(r, g))));
        s = 1.0f; c = 1.0f; p = 0.0f;
        for (i = m; i <= l - 1; i++) {
            f = FMUL(s, e[i - 1]); b = FMUL(c, e[i - 1]);
            slartgf(g, f, &c, &s, &r);
            if (i != m) e[i - 2] = r;
            g = FSUB(d[i - 1], p);
            r = FMAF(FSUB(d[i], g), s, FMUL(FMUL(2.0f, c), b));
            p = FMUL(s, r);
            d[i - 1] = FADD(g, p);
            g = FMAF(c, r, -b);
            wc[i - m] = c;
            ws[i - m] = s;
        }
        mm = l - m + 1;
        for (j = 1; j <= mm - 1; j++) {
            float cj = wc[j - 1], sj = ws[j - 1];
            for (i = 0; i < 3; i++) {
                t = z[i][m + j - 1];
                z[i][m + j - 1] = FMAF(cj, t, -FMUL(sj, z[i][m + j - 2]));
                z[i][m + j - 2] = FMAF(sj, t,  FMUL(cj, z[i][m + j - 2]));
            }
        }
        d[l - 1] = FSUB(d[l - 1], p);
        e[l - 2] = g;
        goto L90;
L130:
        d[l - 1] = p; l--;
        if (l >= lend) goto L90;
        goto L140;
    }
L140:
    if (iscale == 1) {
        mul = FDIV(anorm, ssfmax);
        for (i = lsv; i <= lendsv; i++) d[i - 1] = FMUL(d[i - 1], mul);
        for (i = lsv; i <= lendsv - 1; i++) e[i - 1] = FMUL(e[i - 1], mul);
    } else if (iscale == 2) {
        mul = FDIV(anorm, ssfmin);
        for (i = lsv; i <= lendsv; i++) d[i - 1] = FMUL(d[i - 1], mul);
        for (i = lsv; i <= lendsv - 1; i++) e[i - 1] = FMUL(e[i - 1], mul);
    }
    if (jtot < nmaxit) goto L10;
    goto L190;
L160:
    for (ii = 2; ii <= n; ii++) {
        i = ii - 1; k = i; p = d[i - 1];
        for (j = ii; j <= n; j++) {
            if (d[j - 1] < p) { k = j; p = d[j - 1]; }
        }
        if (k != i) {
            d[k - 1] = d[i - 1]; d[i - 1] = p;
            for (int rr = 0; rr < 3; rr++) {
                t = z[rr][i - 1]; z[rr][i - 1] = z[rr][k - 1]; z[rr][k - 1] = t;
            }
        }
    }
L190:
    return;
}

// ---------------------------------------------------------------------------
// Kernel 1: pack (x,y,z,||p||^2) STRICT + cell id + count
// ---------------------------------------------------------------------------
__global__ void pack_kernel(const float* __restrict__ pts, int n) {
    int i = blockIdx.x * blockDim.x + threadIdx.x;
    if (i < n) {
        float x = pts[3 * i + 0];
        float y = pts[3 * i + 1];
        float z = pts[3 * i + 2];
        float sq = FADD(FADD(FMUL(x, x), FMUL(y, y)), FMUL(z, z));
        g_pts4[i] = make_float4(x, y, z, sq);
        int cx = min(GRID - 1, max(0, (int)(x * (float)GRID)));
        int cy = min(GRID - 1, max(0, (int)(y * (float)GRID)));
        int cz = min(GRID - 1, max(0, (int)(z * (float)GRID)));
        int cid = (cz * GRID + cy) * GRID + cx;
        g_cell[i] = cid;
        atomicAdd(&g_cnt[cid], 1);
    }
}

// ---------------------------------------------------------------------------
// Kernel 2: exclusive scan of 4096 cell counts (single block, 1024 threads)
// ---------------------------------------------------------------------------
__global__ void scan_kernel() {
    __shared__ int sh[1024];
    int t = threadIdx.x;
    int c0 = g_cnt[4 * t + 0];
    int c1 = g_cnt[4 * t + 1];
    int c2 = g_cnt[4 * t + 2];
    int c3 = g_cnt[4 * t + 3];
    int sum = c0 + c1 + c2 + c3;
    sh[t] = sum;
    __syncthreads();
    for (int off = 1; off < 1024; off <<= 1) {
        int v = (t >= off) ? sh[t - off] : 0;
        __syncthreads();
        sh[t] += v;
        __syncthreads();
    }
    int excl = sh[t] - sum;
    g_off[4 * t + 0] = excl;
    g_off[4 * t + 1] = excl + c0;
    g_off[4 * t + 2] = excl + c0 + c1;
    g_off[4 * t + 3] = excl + c0 + c1 + c2;
    g_ptr[4 * t + 0] = excl;
    g_ptr[4 * t + 1] = excl + c0;
    g_ptr[4 * t + 2] = excl + c0 + c1;
    g_ptr[4 * t + 3] = excl + c0 + c1 + c2;
}

// ---------------------------------------------------------------------------
// Kernel 3: scatter points into cell-sorted order
// ---------------------------------------------------------------------------
__global__ void scatter_kernel(int n) {
    int i = blockIdx.x * blockDim.x + threadIdx.x;
    if (i < n) {
        int c = g_cell[i];
        int pos = atomicAdd(&g_ptr[c], 1);
        g_sorted[pos] = g_pts4[i];
        g_sidx[pos] = i;
    }
}

// ---------------------------------------------------------------------------
// Kernel 4 (FUSED, 8 lanes per query): cooperative grid 5-NN + LRF.
// - 8-lane group scans cells cooperatively (group-uniform bounds, no
//   divergence); per-lane stable (d2,idx) top-5; 5-round lex-min shuffle
//   merge = global stable top-5 (identical set to serial version).
// - Group leader runs the FROZEN lrf bit recipe.
// ---------------------------------------------------------------------------
__global__ void knn_lrf_kernel(float* __restrict__ out, int n) {
    int T = blockIdx.x * blockDim.x + threadIdx.x;
    int qid = T >> 3;
    int lg = T & 7;
    if (qid >= n) return;
    unsigned gmask = 0xFFu << (8 * ((threadIdx.x & 31) >> 3));

    float4 q = g_sorted[qid];
    int qi = g_sidx[qid];

    int cx = min(GRID - 1, max(0, (int)(q.x * (float)GRID)));
    int cy = min(GRID - 1, max(0, (int)(q.y * (float)GRID)));
    int cz = min(GRID - 1, max(0, (int)(q.z * (float)GRID)));

    float bd0, bd1, bd2, bd3, bd4;
    int   bi0, bi1, bi2, bi3, bi4;

    for (int Rmax = 1; Rmax <= GRID - 1; Rmax++) {
        // per-lane local stable top-5 (ascending lex (d2, idx))
        float ld0 = INFINITY, ld1 = INFINITY, ld2 = INFINITY, ld3 = INFINITY, ld4 = INFINITY;
        int   li0 = 0x7FFFFFFF, li1 = 0x7FFFFFFF, li2 = 0x7FFFFFFF, li3 = 0x7FFFFFFF, li4 = 0x7FFFFFFF;

        int z0 = max(cz - Rmax, 0), z1 = min(cz + Rmax, GRID - 1);
        int y0 = max(cy - Rmax, 0), y1 = min(cy + Rmax, GRID - 1);
        int x0 = max(cx - Rmax, 0), x1 = min(cx + Rmax, GRID - 1);
        for (int zz = z0; zz <= z1; zz++)
            for (int yy = y0; yy <= y1; yy++) {
                int rowbase = (zz * GRID + yy) * GRID;
                for (int xx = x0; xx <= x1; xx++) {
                    int cid = rowbase + xx;
                    int a = g_off[cid];
                    int b = a + g_cnt[cid];
                    for (int t = a + lg; t < b; t += 8) {
                        float4 p = g_sorted[t];
                        int idx = g_sidx[t];
                        float dot = FADD(FADD(FMUL(q.x, p.x), FMUL(q.y, p.y)), FMUL(q.z, p.z));
                        float d2 = FSUB(FADD(q.w, p.w), FMUL(2.0f, dot));
                        if (d2 < ld4 || (d2 == ld4 && idx < li4)) {
                            if (d2 < ld3 || (d2 == ld3 && idx < li3)) {
                                ld4 = ld3; li4 = li3;
                                if (d2 < ld2 || (d2 == ld2 && idx < li2)) {
                                    ld3 = ld2; li3 = li2;
                                    if (d2 < ld1 || (d2 == ld1 && idx < li1)) {
                                        ld2 = ld1; li2 = li1;
                                        if (d2 < ld0 || (d2 == ld0 && idx < li0)) {
                                            ld1 = ld0; li1 = li0;
                                            ld0 = d2; li0 = idx;
                                        } else { ld1 = d2; li1 = idx; }
                                    } else { ld2 = d2; li2 = idx; }
                                } else { ld3 = d2; li3 = idx; }
                            } else { ld4 = d2; li4 = idx; }
                        }
                    }
                }
            }

        // ---- 5-round group lex-min merge ----
        #pragma unroll
        for (int r = 0; r < 5; r++) {
            float cd = ld0;
            int   ci = li0;
            #pragma unroll
            for (int off = 1; off < 8; off <<= 1) {
                float od = __shfl_xor_sync(gmask, cd, off);
                int   oi = __shfl_xor_sync(gmask, ci, off);
                if (od < cd || (od == cd && oi < ci)) { cd = od; ci = oi; }
            }
            // record winner (all lanes)
            if (r == 0) { bd0 = cd; bi0 = ci; }
            else if (r == 1) { bd1 = cd; bi1 = ci; }
            else if (r == 2) { bd2 = cd; bi2 = ci; }
            else if (r == 3) { bd3 = cd; bi3 = ci; }
            else { bd4 = cd; bi4 = ci; }
            // owning lane pops its head
            if (ld0 == cd && li0 == ci) {
                ld0 = ld1; li0 = li1;
                ld1 = ld2; li1 = li2;
                ld2 = ld3; li2 = li3;
                ld3 = ld4; li3 = li4;
                ld4 = INFINITY; li4 = 0x7FFFFFFF;
            }
        }

        float guard = (float)Rmax * CELLH;
        if (bd4 < guard * guard - 1e-5f) break;
    }

    if (lg != 0) return;

    // =======================================================================
    // LRF (FROZEN bit recipe) — group leader only
    // =======================================================================
    int nbr[KNBR] = { bi0, bi1, bi2, bi3, bi4 };
    (void)bd0; (void)bd1; (void)bd2; (void)bd3;
    float dx[KNBR], dy[KNBR], dz[KNBR];
    #pragma unroll
    for (int k = 0; k < KNBR; k++) {
        float4 p = g_pts4[nbr[k]];
        dx[k] = FSUB(p.x, q.x);
        dy[k] = FSUB(p.y, q.y);
        dz[k] = FSUB(p.z, q.z);
    }
    float sxm = FADD(FADD(FADD(FADD(dx[0], dx[1]), dx[2]), dx[3]), dx[4]);
    float sym = FADD(FADD(FADD(FADD(dy[0], dy[1]), dy[2]), dy[3]), dy[4]);
    float szm = FADD(FADD(FADD(FADD(dz[0], dz[1]), dz[2]), dz[3]), dz[4]);
    float mx = FDIV(sxm, 5.0f);
    float my = FDIV(sym, 5.0f);
    float mz = FDIV(szm, 5.0f);

    float cxa[KNBR], cya[KNBR], cza[KNBR];
    #pragma unroll
    for (int k = 0; k < KNBR; k++) {
        cxa[k] = FSUB(dx[k], mx);
        cya[k] = FSUB(dy[k], my);
        cza[k] = FSUB(dz[k], mz);
    }
    float c00 = 0.f, c10 = 0.f, c20 = 0.f, c11 = 0.f, c21 = 0.f, c22 = 0.f;
    #pragma unroll
    for (int k = 0; k < KNBR; k++) {
        c00 = FMAF(cxa[k], cxa[k], c00);
        c10 = FMAF(cya[k], cxa[k], c10);
        c20 = FMAF(cza[k], cxa[k], c20);
        c11 = FMAF(cya[k], cya[k], c11);
        c21 = FMAF(cza[k], cya[k], c21);
        c22 = FMAF(cza[k], cza[k], c22);
    }
    c00 = FDIV(c00, 5.0f); c10 = FDIV(c10, 5.0f); c20 = FDIV(c20, 5.0f);
    c11 = FDIV(c11, 5.0f); c21 = FDIV(c21, 5.0f); c22 = FDIV(c22, 5.0f);

    // ---- ssytd2 'L', n=3 ----
    float e0, e1s, tau = 0.0f, v2 = 0.0f;
    float a11 = c11, a21 = c21, a22 = c22;
    {
        float alpha = c10;
        float xnorm = FSQRT(FMUL(c20, c20));
        if (xnorm == 0.0f) {
            tau = 0.0f;
            e0 = alpha;
        } else {
            float beta = -f_sign(slapy2f(alpha, xnorm), alpha);
            tau = FDIV(FSUB(beta, alpha), beta);
            v2  = FMUL(c20, FDIV(1.0f, FSUB(alpha, beta)));
            e0  = beta;
            float y1 = FMAF(tau, FMUL(a21, v2), FMUL(tau, a11));
            float y2 = FMAF(FMUL(tau, v2), a22, FMUL(tau, a21));
            float sdot = FMAF(y2, v2, y1);
            float ac = FMUL(FMUL(-0.5f, tau), sdot);
            y1 = FMAF(ac, 1.0f, y1);
            y2 = FMAF(ac, v2, y2);
            a11 = FMAF(y1, -1.0f, FMAF(1.0f, -y1, a11));
            a21 = FMAF(y2, -1.0f, FMAF(v2,  -y1, a21));
            a22 = FMAF(y2, -v2,   FMAF(v2,  -y2, a22));
        }
        e1s = a21;
    }

    float d[3] = { c00, a11, a22 };
    float e[2] = { e0, e1s };
    float z[3][3] = { {1.f,0.f,0.f}, {0.f,1.f,0.f}, {0.f,0.f,1.f} };

    steqr3(d, e, z);

    if (tau != 0.0f) {
        #pragma unroll
        for (int jc = 0; jc < 3; jc++) {
            float w = FMAF(z[2][jc], v2, z[1][jc]);
            float tneg = FMUL(-tau, w);
            z[1][jc] = FMAF(1.0f, tneg, z[1][jc]);
            z[2][jc] = FMAF(v2,  tneg, z[2][jc]);
        }
    }

    float xr0 = z[2][0], xr1 = z[2][1], xr2 = z[2][2];
    float zr0 = z[0][0], zr1 = z[0][1], zr2 = z[0][2];

    int cx_cnt = 0, cz_cnt = 0;
    #pragma unroll
    for (int k = 0; k < KNBR; k++) {
        float wx = FSUB(dx[k], q.x);
        float wy = FSUB(dy[k], q.y);
        float wz = FSUB(dz[k], q.z);
        float dotx = FMAF(wz, xr2, FMAF(wy, xr1, FMUL(wx, xr0)));
        float dotz = FMAF(wz, zr2, FMAF(wy, zr1, FMUL(wx, zr0)));
        if (dotx >= -EPSV) cx_cnt++;
        if (dotz >= -EPSV) cz_cnt++;
    }
    float sx = (2 * cx_cnt >= KNBR) ? 1.0f : -1.0f;
    float sz = (2 * cz_cnt >= KNBR) ? 1.0f : -1.0f;

    float xa0 = FMUL(xr0, sx), xa1 = FMUL(xr1, sx), xa2 = FMUL(xr2, sx);
    float za0 = FMUL(zr0, sz), za1 = FMUL(zr1, sz), za2 = FMUL(zr2, sz);
    float ya0 = FSUB(FMUL(za1, xa2), FMUL(za2, xa1));
    float ya1 = FSUB(FMUL(za2, xa0), FMUL(za0, xa2));
    float ya2 = FSUB(FMUL(za0, xa1), FMUL(za1, xa0));

    float* o = out + (size_t)qi * 9;
    o[0] = xa0; o[1] = xa1; o[2] = xa2;
    o[3] = ya0; o[4] = ya1; o[5] = ya2;
    o[6] = za0; o[7] = za1; o[8] = za2;
}

// ---------------------------------------------------------------------------
extern "C" void kernel_launch(void* const* d_in, const int* in_sizes, int n_in,
                              void* d_out, int out_size) {
    const float* pts = (const float*)d_in[0];
    float* out = (float*)d_out;
    int n = in_sizes[0] / 3;
    if (n > NPTS_MAX) n = NPTS_MAX;

    void* cnt_ptr = nullptr;
    cudaGetSymbolAddress(&cnt_ptr, g_cnt);
    cudaMemsetAsync(cnt_ptr, 0, NCELL * sizeof(int));

    pack_kernel<<<(n + 255) / 256, 256>>>(pts, n);
    scan_kernel<<<1, 1024>>>();
    scatter_kernel<<<(n + 255) / 256, 256>>>(n);
    int threads = n * 8;
    knn_lrf_kernel<<<(threads + 255) / 256, 256>>>(out, n);
}

// round 16
// speedup vs baseline: 2.0000x; 1.3901x over previous
#include <cuda_runtime.h>
#include <math.h>

#define NPTS_MAX 16384
#define KNBR 5
#define EPSV 1e-5f
#define GRID 16
#define NCELL (GRID * GRID * GRID)
#define CELLH 0.0625f

#define FMUL __fmul_rn
#define FADD __fadd_rn
#define FSUB __fsub_rn
#define FDIV __fdiv_rn
#define FMAF __fmaf_rn
#define FSQRT __fsqrt_rn

typedef unsigned long long u64;
typedef unsigned int u32;

__device__ float4 g_pts4[NPTS_MAX];
__device__ int    g_cnt[NCELL];
__device__ int    g_off[NCELL];
__device__ int    g_ptr[NCELL];
__device__ int    g_cell[NPTS_MAX];
__device__ float4 g_sorted[NPTS_MAX];
__device__ int    g_sidx[NPTS_MAX];

// monotone float->u32 (strictly order-preserving; d2 never -0.0 or NaN here)
__device__ __forceinline__ u32 f2ord(float f) {
    u32 u = __float_as_uint(f);
    u32 mask = (u & 0x80000000u) ? 0xFFFFFFFFu : 0x80000000u;
    return u ^ mask;
}
__device__ __forceinline__ float ord2f(u32 m) {
    u32 u = (m & 0x80000000u) ? (m ^ 0x80000000u) : ~m;
    return __uint_as_float(u);
}

// ---------------------------------------------------------------------------
// LAPACK fp32 helpers — FROZEN bit recipe
// ---------------------------------------------------------------------------

__device__ __forceinline__ float f_sign(float a, float b) {
    return copysignf(fabsf(a), b);
}

__device__ __forceinline__ float slapy2f(float x, float y) {
    float xa = fabsf(x), ya = fabsf(y);
    float w = fmaxf(xa, ya), zz = fminf(xa, ya);
    if (zz == 0.0f) return w;
    float t = FDIV(zz, w);
    return FMUL(w, FSQRT(FMAF(t, t, 1.0f)));
}

__device__ void slartgf(float f, float g, float* c, float* s, float* r) {
    const float safmin = 1.17549435e-38f;
    const float safmax = 8.50705917e37f;
    const float rtmin  = 1.08420217e-19f;
    const float rtmax  = 6.52252447e18f;
    if (g == 0.0f) {
        *c = 1.0f; *s = 0.0f; *r = f;
    } else if (f == 0.0f) {
        *c = 0.0f;
        *s = (g >= 0.0f) ? 1.0f : -1.0f;
        *r = fabsf(g);
    } else {
        float f1 = fabsf(f), g1 = fabsf(g);
        if (f1 > rtmin && f1 < rtmax && g1 > rtmin && g1 < rtmax) {
            float d = FSQRT(FMAF(f, f, FMUL(g, g)));
            *c = FDIV(f1, d);
            *r = f_sign(d, f);
            *s = FDIV(g, *r);
        } else {
            float u = fminf(safmax, fmaxf(safmin, fmaxf(f1, g1)));
            float fs = FDIV(f, u), gs = FDIV(g, u);
            float d = FSQRT(FMAF(fs, fs, FMUL(gs, gs)));
            *c = FDIV(fabsf(fs), d);
            *r = f_sign(d, f);
            *s = FDIV(gs, *r);
            *r = FMUL(*r, u);
        }
    }
}

__device__ void slaev2f(float a, float b, float c_, float* rt1, float* rt2,
                        float* cs1, float* sn1) {
    float sm = FADD(a, c_);
    float df = FSUB(a, c_);
    float adf = fabsf(df);
    float tb = FADD(b, b);
    float ab = fabsf(tb);
    float acmx, acmn;
    if (fabsf(a) > fabsf(c_)) { acmx = a; acmn = c_; } else { acmx = c_; acmn = a; }
    float rt;
    if (adf > ab) {
        float t = FDIV(ab, adf);
        rt = FMUL(adf, FSQRT(FMAF(t, t, 1.0f)));
    } else if (adf < ab) {
        float t = FDIV(adf, ab);
        rt = FMUL(ab, FSQRT(FMAF(t, t, 1.0f)));
    } else {
        rt = FMUL(ab, 1.41421356f);
    }
    int sgn1;
    if (sm < 0.0f) {
        *rt1 = FMUL(0.5f, FSUB(sm, rt)); sgn1 = -1;
        float q1 = FDIV(acmx, *rt1), q2 = FDIV(b, *rt1);
        *rt2 = FMAF(q1, acmn, -FMUL(q2, b));
    } else if (sm > 0.0f) {
        *rt1 = FMUL(0.5f, FADD(sm, rt)); sgn1 = 1;
        float q1 = FDIV(acmx, *rt1), q2 = FDIV(b, *rt1);
        *rt2 = FMAF(q1, acmn, -FMUL(q2, b));
    } else {
        *rt1 = FMUL(0.5f, rt); *rt2 = FMUL(-0.5f, rt); sgn1 = 1;
    }
    float cs; int sgn2;
    if (df >= 0.0f) { cs = FADD(df, rt); sgn2 = 1; }
    else            { cs = FSUB(df, rt); sgn2 = -1; }
    float acs = fabsf(cs);
    if (acs > ab) {
        float ct = FDIV(-tb, cs);
        *sn1 = FDIV(1.0f, FSQRT(FMAF(ct, ct, 1.0f)));
        *cs1 = FMUL(ct, *sn1);
    } else {
        if (ab == 0.0f) { *cs1 = 1.0f; *sn1 = 0.0f; }
        else {
            float tn = FDIV(-cs, tb);
            *cs1 = FDIV(1.0f, FSQRT(FMAF(tn, tn, 1.0f)));
            *sn1 = FMUL(tn, *cs1);
        }
    }
    if (sgn1 == sgn2) {
        float tn = *cs1;
        *cs1 = -(*sn1);
        *sn1 = tn;
    }
}

// SSTEQR compz='I', n=3.
__device__ void steqr3(float d[3], float e[2], float z[3][3]) {
    const int   n      = 3;
    const float eps    = 5.96046448e-08f;
    const float eps2   = 3.55271368e-15f;
    const float safmin = 1.17549435e-38f;
    const float ssfmax = 3.07445735e18f;
    const float ssfmin = 3.05175781e-05f;
    const int   nmaxit = 90;

    float wc[2], ws[2];
    int   jtot = 0, l1 = 1;
    int   l, lsv, lend, lendsv, m, mm, i, ii, j, k, iscale;
    float anorm = 0.0f, p, g, r, c, s, f, b, rt1, rt2, tst, mul, t;

L10:
    if (l1 > n) goto L160;
    if (l1 > 1) e[l1 - 2] = 0.0f;
    if (l1 <= n - 1) {
        for (m = l1; m <= n - 1; m++) {
            tst = fabsf(e[m - 1]);
            if (tst == 0.0f) goto L30;
            {
                float thr = FMUL(FMUL(FSQRT(fabsf(d[m - 1])), FSQRT(fabsf(d[m]))), eps);
                if (tst <= thr) { e[m - 1] = 0.0f; goto L30; }
            }
        }
    }
    m = n;
L30:
    l = l1; lsv = l; lend = m; lendsv = lend; l1 = m + 1;
    if (lend == l) goto L10;

    anorm = fabsf(d[lend - 1]);
    for (i = l; i <= lend - 1; i++) {
        anorm = fmaxf(anorm, fabsf(d[i - 1]));
        anorm = fmaxf(anorm, fabsf(e[i - 1]));
    }
    iscale = 0;
    if (anorm == 0.0f) goto L10;
    if (anorm > ssfmax) {
        iscale = 1; mul = FDIV(ssfmax, anorm);
        for (i = l; i <= lend; i++) d[i - 1] = FMUL(d[i - 1], mul);
        for (i = l; i <= lend - 1; i++) e[i - 1] = FMUL(e[i - 1], mul);
    } else if (anorm < ssfmin) {
        iscale = 2; mul = FDIV(ssfmin, anorm);
        for (i = l; i <= lend; i++) d[i - 1] = FMUL(d[i - 1], mul);
        for (i = l; i <= lend - 1; i++) e[i - 1] = FMUL(e[i - 1], mul);
    }

    if (fabsf(d[lend - 1]) < fabsf(d[l - 1])) { lend = lsv; l = lendsv; }

    if (lend > l) {
L40:
        if (l != lend) {
            for (m = l; m <= lend - 1; m++) {
                tst = FMUL(e[m - 1], e[m - 1]);
                float rhs = FMAF(FMUL(eps2, fabsf(d[m - 1])), fabsf(d[m]), safmin);
                if (tst <= rhs) goto L60;
            }
        }
        m = lend;
L60:
        if (m < lend) e[m - 1] = 0.0f;
        p = d[l - 1];
        if (m == l) goto L80;
        if (m == l + 1) {
            slaev2f(d[l - 1], e[l - 1], d[l], &rt1, &rt2, &c, &s);
            for (i = 0; i < 3; i++) {
                t = z[i][l];
                z[i][l]     = FMAF(c, t, -FMUL(s, z[i][l - 1]));
                z[i][l - 1] = FMAF(s, t,  FMUL(c, z[i][l - 1]));
            }
            d[l - 1] = rt1; d[l] = rt2; e[l - 1] = 0.0f;
            l += 2;
            if (l <= lend) goto L40;
            goto L140;
        }
        if (jtot == nmaxit) goto L140;
        jtot++;
        g = FDIV(FSUB(d[l], p), FMUL(2.0f, e[l - 1]));
        r = slapy2f(g, 1.0f);
        g = FADD(FSUB(d[m - 1], p), FDIV(e[l - 1], FADD(g, f_sign(r, g))));
        s = 1.0f; c = 1.0f; p = 0.0f;
        for (i = m - 1; i >= l; i--) {
            f = FMUL(s, e[i - 1]); b = FMUL(c, e[i - 1]);
            slartgf(g, f, &c, &s, &r);
            if (i != m - 1) e[i] = r;
            g = FSUB(d[i], p);
            r = FMAF(FSUB(d[i - 1], g), s, FMUL(FMUL(2.0f, c), b));
            p = FMUL(s, r);
            d[i] = FADD(g, p);
            g = FMAF(c, r, -b);
            wc[i - l] = c;
            ws[i - l] = -s;
        }
        mm = m - l + 1;
        for (j = mm - 1; j >= 1; j--) {
            float cj = wc[j - 1], sj = ws[j - 1];
            for (i = 0; i < 3; i++) {
                t = z[i][l + j - 1];
                z[i][l + j - 1] = FMAF(cj, t, -FMUL(sj, z[i][l + j - 2]));
                z[i][l + j - 2] = FMAF(sj, t,  FMUL(cj, z[i][l + j - 2]));
            }
        }
        d[l - 1] = FSUB(d[l - 1], p);
        e[l - 1] = g;
        goto L40;
L80:
        d[l - 1] = p; l++;
        if (l <= lend) goto L40;
        goto L140;
    } else {
L90:
        if (l != lend) {
            for (m = l; m >= lend + 1; m--) {
                tst = FMUL(e[m - 2], e[m - 2]);
                float rhs = FMAF(FMUL(eps2, fabsf(d[m - 1])), fabsf(d[m - 2]), safmin);
                if (tst <= rhs) goto L110;
            }
        }
        m = lend;
L110:
        if (m > lend) e[m - 2] = 0.0f;
        p = d[l - 1];
        if (m == l) goto L130;
        if (m == l - 1) {
            slaev2f(d[l - 2], e[l - 2], d[l - 1], &rt1, &rt2, &c, &s);
            for (i = 0; i < 3; i++) {
                t = z[i][l - 1];
                z[i][l - 1] = FMAF(c, t, -FMUL(s, z[i][l - 2]));
                z[i][l - 2] = FMAF(s, t,  FMUL(c, z[i][l - 2]));
            }
            d[l - 2] = rt1; d[l - 1] = rt2; e[l - 2] = 0.0f;
            l -= 2;
            if (l >= lend) goto L90;
            goto L140;
        }
        if (jtot == nmaxit) goto L140;
        jtot++;
        g = FDIV(FSUB(d[l - 2], p), FMUL(2.0f, e[l - 2]));
        r = slapy2f(g, 1.0f);
        g = FADD(FSUB(d[m - 1], p), FDIV(e[l - 2], FADD(g, f_sign(r, g))));
        s = 1.0f; c = 1.0f; p = 0.0f;
        for (i = m; i <= l - 1; i++) {
            f = FMUL(s, e[i - 1]); b = FMUL(c, e[i - 1]);
            slartgf(g, f, &c, &s, &r);
            if (i != m) e[i - 2] = r;
            g = FSUB(d[i - 1], p);
            r = FMAF(FSUB(d[i], g), s, FMUL(FMUL(2.0f, c), b));
            p = FMUL(s, r);
            d[i - 1] = FADD(g, p);
            g = FMAF(c, r, -b);
            wc[i - m] = c;
            ws[i - m] = s;
        }
        mm = l - m + 1;
        for (j = 1; j <= mm - 1; j++) {
            float cj = wc[j - 1], sj = ws[j - 1];
            for (i = 0; i < 3; i++) {
                t = z[i][m + j - 1];
                z[i][m + j - 1] = FMAF(cj, t, -FMUL(sj, z[i][m + j - 2]));
                z[i][m + j - 2] = FMAF(sj, t,  FMUL(cj, z[i][m + j - 2]));
            }
        }
        d[l - 1] = FSUB(d[l - 1], p);
        e[l - 2] = g;
        goto L90;
L130:
        d[l - 1] = p; l--;
        if (l >= lend) goto L90;
        goto L140;
    }
L140:
    if (iscale == 1) {
        mul = FDIV(anorm, ssfmax);
        for (i = lsv; i <= lendsv; i++) d[i - 1] = FMUL(d[i - 1], mul);
        for (i = lsv; i <= lendsv - 1; i++) e[i - 1] = FMUL(e[i - 1], mul);
    } else if (iscale == 2) {
        mul = FDIV(anorm, ssfmin);
        for (i = lsv; i <= lendsv; i++) d[i - 1] = FMUL(d[i - 1], mul);
        for (i = lsv; i <= lendsv - 1; i++) e[i - 1] = FMUL(e[i - 1], mul);
    }
    if (jtot < nmaxit) goto L10;
    goto L190;
L160:
    for (ii = 2; ii <= n; ii++) {
        i = ii - 1; k = i; p = d[i - 1];
        for (j = ii; j <= n; j++) {
            if (d[j - 1] < p) { k = j; p = d[j - 1]; }
        }
        if (k != i) {
            d[k - 1] = d[i - 1]; d[i - 1] = p;
            for (int rr = 0; rr < 3; rr++) {
                t = z[rr][i - 1]; z[rr][i - 1] = z[rr][k - 1]; z[rr][k - 1] = t;
            }
        }
    }
L190:
    return;
}

// ---------------------------------------------------------------------------
// Kernel 1: pack (x,y,z,||p||^2) STRICT + cell id + count
// ---------------------------------------------------------------------------
__global__ void pack_kernel(const float* __restrict__ pts, int n) {
    int i = blockIdx.x * blockDim.x + threadIdx.x;
    if (i < n) {
        float x = pts[3 * i + 0];
        float y = pts[3 * i + 1];
        float z = pts[3 * i + 2];
        float sq = FADD(FADD(FMUL(x, x), FMUL(y, y)), FMUL(z, z));
        g_pts4[i] = make_float4(x, y, z, sq);
        int cx = min(GRID - 1, max(0, (int)(x * (float)GRID)));
        int cy = min(GRID - 1, max(0, (int)(y * (float)GRID)));
        int cz = min(GRID - 1, max(0, (int)(z * (float)GRID)));
        int cid = (cz * GRID + cy) * GRID + cx;
        g_cell[i] = cid;
        atomicAdd(&g_cnt[cid], 1);
    }
}

// ---------------------------------------------------------------------------
// Kernel 2: exclusive scan of 4096 cell counts
// ---------------------------------------------------------------------------
__global__ void scan_kernel() {
    __shared__ int sh[1024];
    int t = threadIdx.x;
    int c0 = g_cnt[4 * t + 0];
    int c1 = g_cnt[4 * t + 1];
    int c2 = g_cnt[4 * t + 2];
    int c3 = g_cnt[4 * t + 3];
    int sum = c0 + c1 + c2 + c3;
    sh[t] = sum;
    __syncthreads();
    for (int off = 1; off < 1024; off <<= 1) {
        int v = (t >= off) ? sh[t - off] : 0;
        __syncthreads();
        sh[t] += v;
        __syncthreads();
    }
    int excl = sh[t] - sum;
    g_off[4 * t + 0] = excl;
    g_off[4 * t + 1] = excl + c0;
    g_off[4 * t + 2] = excl + c0 + c1;
    g_off[4 * t + 3] = excl + c0 + c1 + c2;
    g_ptr[4 * t + 0] = excl;
    g_ptr[4 * t + 1] = excl + c0;
    g_ptr[4 * t + 2] = excl + c0 + c1;
    g_ptr[4 * t + 3] = excl + c0 + c1 + c2;
}

// ---------------------------------------------------------------------------
// Kernel 3: scatter points into cell-sorted order
// ---------------------------------------------------------------------------
__global__ void scatter_kernel(int n) {
    int i = blockIdx.x * blockDim.x + threadIdx.x;
    if (i < n) {
        int c = g_cell[i];
        int pos = atomicAdd(&g_ptr[c], 1);
        g_sorted[pos] = g_pts4[i];
        g_sidx[pos] = i;
    }
}

// ---------------------------------------------------------------------------
// Kernel 4 (FUSED, 8 lanes/query): cooperative grid 5-NN + LRF.
// u64 packed keys (order-equivalent to lex (d2,idx)); contiguous x-span scan.
// ---------------------------------------------------------------------------
__global__ void __launch_bounds__(256, 1)
knn_lrf_kernel(float* __restrict__ out, int n) {
    int T = blockIdx.x * blockDim.x + threadIdx.x;
    int qid = T >> 3;
    int lg = T & 7;
    if (qid >= n) return;
    unsigned gmask = 0xFFu << (8 * ((threadIdx.x & 31) >> 3));

    float4 q = g_sorted[qid];
    int qi = g_sidx[qid];

    int cx = min(GRID - 1, max(0, (int)(q.x * (float)GRID)));
    int cy = min(GRID - 1, max(0, (int)(q.y * (float)GRID)));
    int cz = min(GRID - 1, max(0, (int)(q.z * (float)GRID)));

    u64 w0, w1, w2, w3, w4;   // merged global top-5 keys

    for (int Rmax = 1; Rmax <= GRID - 1; Rmax++) {
        u64 l0 = ~0ULL, l1 = ~0ULL, l2 = ~0ULL, l3 = ~0ULL, l4 = ~0ULL;

        int z0 = max(cz - Rmax, 0), z1 = min(cz + Rmax, GRID - 1);
        int y0 = max(cy - Rmax, 0), y1 = min(cy + Rmax, GRID - 1);
        int x0 = max(cx - Rmax, 0), x1 = min(cx + Rmax, GRID - 1);
        for (int zz = z0; zz <= z1; zz++)
            for (int yy = y0; yy <= y1; yy++) {
                int rowbase = (zz * GRID + yy) * GRID;
                int a = g_off[rowbase + x0];
                int b = g_off[rowbase + x1] + g_cnt[rowbase + x1];
                for (int t = a + lg; t < b; t += 8) {
                    float4 p = g_sorted[t];
                    int idx = g_sidx[t];
                    float dot = FADD(FADD(FMUL(q.x, p.x), FMUL(q.y, p.y)), FMUL(q.z, p.z));
                    float d2 = FSUB(FADD(q.w, p.w), FMUL(2.0f, dot));
                    u64 key = ((u64)f2ord(d2) << 32) | (u32)idx;
                    if (key < l4) {
                        if (key < l3) {
                            l4 = l3;
                            if (key < l2) {
                                l3 = l2;
                                if (key < l1) {
                                    l2 = l1;
                                    if (key < l0) { l1 = l0; l0 = key; }
                                    else l1 = key;
                                } else l2 = key;
                            } else l3 = key;
                        } else l4 = key;
                    }
                }
            }

        // ---- 5-round group min-merge ----
        #pragma unroll
        for (int r = 0; r < 5; r++) {
            u64 c = l0;
            #pragma unroll
            for (int off = 1; off < 8; off <<= 1) {
                u64 o = __shfl_xor_sync(gmask, c, off);
                if (o < c) c = o;
            }
            if (r == 0) w0 = c;
            else if (r == 1) w1 = c;
            else if (r == 2) w2 = c;
            else if (r == 3) w3 = c;
            else w4 = c;
            if (l0 == c) { l0 = l1; l1 = l2; l2 = l3; l3 = l4; l4 = ~0ULL; }
        }

        float bd4 = ord2f((u32)(w4 >> 32));
        float guard = (float)Rmax * CELLH;
        if (bd4 < guard * guard - 1e-5f) break;
    }

    if (lg != 0) return;

    // =======================================================================
    // LRF (FROZEN bit recipe) — group leader only
    // =======================================================================
    int nbr[KNBR] = { (int)(u32)w0, (int)(u32)w1, (int)(u32)w2,
                      (int)(u32)w3, (int)(u32)w4 };
    float dx[KNBR], dy[KNBR], dz[KNBR];
    #pragma unroll
    for (int k = 0; k < KNBR; k++) {
        float4 p = g_pts4[nbr[k]];
        dx[k] = FSUB(p.x, q.x);
        dy[k] = FSUB(p.y, q.y);
        dz[k] = FSUB(p.z, q.z);
    }
    float sxm = FADD(FADD(FADD(FADD(dx[0], dx[1]), dx[2]), dx[3]), dx[4]);
    float sym = FADD(FADD(FADD(FADD(dy[0], dy[1]), dy[2]), dy[3]), dy[4]);
    float szm = FADD(FADD(FADD(FADD(dz[0], dz[1]), dz[2]), dz[3]), dz[4]);
    float mx = FDIV(sxm, 5.0f);
    float my = FDIV(sym, 5.0f);
    float mz = FDIV(szm, 5.0f);

    float cxa[KNBR], cya[KNBR], cza[KNBR];
    #pragma unroll
    for (int k = 0; k < KNBR; k++) {
        cxa[k] = FSUB(dx[k], mx);
        cya[k] = FSUB(dy[k], my);
        cza[k] = FSUB(dz[k], mz);
    }
    float c00 = 0.f, c10 = 0.f, c20 = 0.f, c11 = 0.f, c21 = 0.f, c22 = 0.f;
    #pragma unroll
    for (int k = 0; k < KNBR; k++) {
        c00 = FMAF(cxa[k], cxa[k], c00);
        c10 = FMAF(cya[k], cxa[k], c10);
        c20 = FMAF(cza[k], cxa[k], c20);
        c11 = FMAF(cya[k], cya[k], c11);
        c21 = FMAF(cza[k], cya[k], c21);
        c22 = FMAF(cza[k], cza[k], c22);
    }
    c00 = FDIV(c00, 5.0f); c10 = FDIV(c10, 5.0f); c20 = FDIV(c20, 5.0f);
    c11 = FDIV(c11, 5.0f); c21 = FDIV(c21, 5.0f); c22 = FDIV(c22, 5.0f);

    // ---- ssytd2 'L', n=3 ----
    float e0, e1s, tau = 0.0f, v2 = 0.0f;
    float a11 = c11, a21 = c21, a22 = c22;
    {
        float alpha = c10;
        float xnorm = FSQRT(FMUL(c20, c20));
        if (xnorm == 0.0f) {
            tau = 0.0f;
            e0 = alpha;
        } else {
            float beta = -f_sign(slapy2f(alpha, xnorm), alpha);
            tau = FDIV(FSUB(beta, alpha), beta);
            v2  = FMUL(c20, FDIV(1.0f, FSUB(alpha, beta)));
            e0  = beta;
            float y1 = FMAF(tau, FMUL(a21, v2), FMUL(tau, a11));
            float y2 = FMAF(FMUL(tau, v2), a22, FMUL(tau, a21));
            float sdot = FMAF(y2, v2, y1);
            float ac = FMUL(FMUL(-0.5f, tau), sdot);
            y1 = FMAF(ac, 1.0f, y1);
            y2 = FMAF(ac, v2, y2);
            a11 = FMAF(y1, -1.0f, FMAF(1.0f, -y1, a11));
            a21 = FMAF(y2, -1.0f, FMAF(v2,  -y1, a21));
            a22 = FMAF(y2, -v2,   FMAF(v2,  -y2, a22));
        }
        e1s = a21;
    }

    float d[3] = { c00, a11, a22 };
    float e[2] = { e0, e1s };
    float z[3][3] = { {1.f,0.f,0.f}, {0.f,1.f,0.f}, {0.f,0.f,1.f} };

    steqr3(d, e, z);

    if (tau != 0.0f) {
        #pragma unroll
        for (int jc = 0; jc < 3; jc++) {
            float w = FMAF(z[2][jc], v2, z[1][jc]);
            float tneg = FMUL(-tau, w);
            z[1][jc] = FMAF(1.0f, tneg, z[1][jc]);
            z[2][jc] = FMAF(v2,  tneg, z[2][jc]);
        }
    }

    float xr0 = z[2][0], xr1 = z[2][1], xr2 = z[2][2];
    float zr0 = z[0][0], zr1 = z[0][1], zr2 = z[0][2];

    int cx_cnt = 0, cz_cnt = 0;
    #pragma unroll
    for (int k = 0; k < KNBR; k++) {
        float wx = FSUB(dx[k], q.x);
        float wy = FSUB(dy[k], q.y);
        float wz = FSUB(dz[k], q.z);
        float dotx = FMAF(wz, xr2, FMAF(wy, xr1, FMUL(wx, xr0)));
        float dotz = FMAF(wz, zr2, FMAF(wy, zr1, FMUL(wx, zr0)));
        if (dotx >= -EPSV) cx_cnt++;
        if (dotz >= -EPSV) cz_cnt++;
    }
    float sx = (2 * cx_cnt >= KNBR) ? 1.0f : -1.0f;
    float sz = (2 * cz_cnt >= KNBR) ? 1.0f : -1.0f;

    float xa0 = FMUL(xr0, sx), xa1 = FMUL(xr1, sx), xa2 = FMUL(xr2, sx);
    float za0 = FMUL(zr0, sz), za1 = FMUL(zr1, sz), za2 = FMUL(zr2, sz);
    float ya0 = FSUB(FMUL(za1, xa2), FMUL(za2, xa1));
    float ya1 = FSUB(FMUL(za2, xa0), FMUL(za0, xa2));
    float ya2 = FSUB(FMUL(za0, xa1), FMUL(za1, xa0));

    float* o = out + (size_t)qi * 9;
    o[0] = xa0; o[1] = xa1; o[2] = xa2;
    o[3] = ya0; o[4] = ya1; o[5] = ya2;
    o[6] = za0; o[7] = za1; o[8] = za2;
}

// ---------------------------------------------------------------------------
extern "C" void kernel_launch(void* const* d_in, const int* in_sizes, int n_in,
                              void* d_out, int out_size) {
    const float* pts = (const float*)d_in[0];
    float* out = (float*)d_out;
    int n = in_sizes[0] / 3;
    if (n > NPTS_MAX) n = NPTS_MAX;

    void* cnt_ptr = nullptr;
    cudaGetSymbolAddress(&cnt_ptr, g_cnt);
    cudaMemsetAsync(cnt_ptr, 0, NCELL * sizeof(int));

    pack_kernel<<<(n + 255) / 256, 256>>>(pts, n);
    scan_kernel<<<1, 1024>>>();
    scatter_kernel<<<(n + 255) / 256, 256>>>(n);
    int threads = n * 8;
    knn_lrf_kernel<<<(threads + 255) / 256, 256>>>(out, n);
}

// round 17
// speedup vs baseline: 2.1469x; 1.0735x over previous
#include <cuda_runtime.h>
#include <math.h>

#define NPTS_MAX 16384
#define KNBR 5
#define EPSV 1e-5f
#define GRID 16
#define NCELL (GRID * GRID * GRID)
#define CELLH 0.0625f

#define FMUL __fmul_rn
#define FADD __fadd_rn
#define FSUB __fsub_rn
#define FDIV __fdiv_rn
#define FMAF __fmaf_rn
#define FSQRT __fsqrt_rn

typedef unsigned long long u64;
typedef unsigned int u32;

__device__ float4 g_pts4[NPTS_MAX];
__device__ int    g_cnt[NCELL];
__device__ int    g_off[NCELL];
__device__ int    g_ptr[NCELL];
__device__ int    g_cell[NPTS_MAX];
__device__ float4 g_sorted[NPTS_MAX];
__device__ int    g_sidx[NPTS_MAX];
__device__ int    g_nbr[NPTS_MAX * KNBR];

// monotone float->u32 (strictly order-preserving; d2 never -0.0 or NaN here)
__device__ __forceinline__ u32 f2ord(float f) {
    u32 u = __float_as_uint(f);
    u32 mask = (u & 0x80000000u) ? 0xFFFFFFFFu : 0x80000000u;
    return u ^ mask;
}
__device__ __forceinline__ float ord2f(u32 m) {
    u32 u = (m & 0x80000000u) ? (m ^ 0x80000000u) : ~m;
    return __uint_as_float(u);
}

// ---------------------------------------------------------------------------
// LAPACK fp32 helpers — FROZEN bit recipe
// ---------------------------------------------------------------------------

__device__ __forceinline__ float f_sign(float a, float b) {
    return copysignf(fabsf(a), b);
}

__device__ __forceinline__ float slapy2f(float x, float y) {
    float xa = fabsf(x), ya = fabsf(y);
    float w = fmaxf(xa, ya), zz = fminf(xa, ya);
    if (zz == 0.0f) return w;
    float t = FDIV(zz, w);
    return FMUL(w, FSQRT(FMAF(t, t, 1.0f)));
}

__device__ void slartgf(float f, float g, float* c, float* s, float* r) {
    const float safmin = 1.17549435e-38f;
    const float safmax = 8.50705917e37f;
    const float rtmin  = 1.08420217e-19f;
    const float rtmax  = 6.52252447e18f;
    if (g == 0.0f) {
        *c = 1.0f; *s = 0.0f; *r = f;
    } else if (f == 0.0f) {
        *c = 0.0f;
        *s = (g >= 0.0f) ? 1.0f : -1.0f;
        *r = fabsf(g);
    } else {
        float f1 = fabsf(f), g1 = fabsf(g);
        if (f1 > rtmin && f1 < rtmax && g1 > rtmin && g1 < rtmax) {
            float d = FSQRT(FMAF(f, f, FMUL(g, g)));
            *c = FDIV(f1, d);
            *r = f_sign(d, f);
            *s = FDIV(g, *r);
        } else {
            float u = fminf(safmax, fmaxf(safmin, fmaxf(f1, g1)));
            float fs = FDIV(f, u), gs = FDIV(g, u);
            float d = FSQRT(FMAF(fs, fs, FMUL(gs, gs)));
            *c = FDIV(fabsf(fs), d);
            *r = f_sign(d, f);
            *s = FDIV(gs, *r);
            *r = FMUL(*r, u);
        }
    }
}

__device__ void slaev2f(float a, float b, float c_, float* rt1, float* rt2,
                        float* cs1, float* sn1) {
    float sm = FADD(a, c_);
    float df = FSUB(a, c_);
    float adf = fabsf(df);
    float tb = FADD(b, b);
    float ab = fabsf(tb);
    float acmx, acmn;
    if (fabsf(a) > fabsf(c_)) { acmx = a; acmn = c_; } else { acmx = c_; acmn = a; }
    float rt;
    if (adf > ab) {
        float t = FDIV(ab, adf);
        rt = FMUL(adf, FSQRT(FMAF(t, t, 1.0f)));
    } else if (adf < ab) {
        float t = FDIV(adf, ab);
        rt = FMUL(ab, FSQRT(FMAF(t, t, 1.0f)));
    } else {
        rt = FMUL(ab, 1.41421356f);
    }
    int sgn1;
    if (sm < 0.0f) {
        *rt1 = FMUL(0.5f, FSUB(sm, rt)); sgn1 = -1;
        float q1 = FDIV(acmx, *rt1), q2 = FDIV(b, *rt1);
        *rt2 = FMAF(q1, acmn, -FMUL(q2, b));
    } else if (sm > 0.0f) {
        *rt1 = FMUL(0.5f, FADD(sm, rt)); sgn1 = 1;
        float q1 = FDIV(acmx, *rt1), q2 = FDIV(b, *rt1);
        *rt2 = FMAF(q1, acmn, -FMUL(q2, b));
    } else {
        *rt1 = FMUL(0.5f, rt); *rt2 = FMUL(-0.5f, rt); sgn1 = 1;
    }
    float cs; int sgn2;
    if (df >= 0.0f) { cs = FADD(df, rt); sgn2 = 1; }
    else            { cs = FSUB(df, rt); sgn2 = -1; }
    float acs = fabsf(cs);
    if (acs > ab) {
        float ct = FDIV(-tb, cs);
        *sn1 = FDIV(1.0f, FSQRT(FMAF(ct, ct, 1.0f)));
        *cs1 = FMUL(ct, *sn1);
    } else {
        if (ab == 0.0f) { *cs1 = 1.0f; *sn1 = 0.0f; }
        else {
            float tn = FDIV(-cs, tb);
            *cs1 = FDIV(1.0f, FSQRT(FMAF(tn, tn, 1.0f)));
            *sn1 = FMUL(tn, *cs1);
        }
    }
    if (sgn1 == sgn2) {
        float tn = *cs1;
        *cs1 = -(*sn1);
        *sn1 = tn;
    }
}

// SSTEQR compz='I', n=3.
__device__ void steqr3(float d[3], float e[2], float z[3][3]) {
    const int   n      = 3;
    const float eps    = 5.96046448e-08f;
    const float eps2   = 3.55271368e-15f;
    const float safmin = 1.17549435e-38f;
    const float ssfmax = 3.07445735e18f;
    const float ssfmin = 3.05175781e-05f;
    const int   nmaxit = 90;

    float wc[2], ws[2];
    int   jtot = 0, l1 = 1;
    int   l, lsv, lend, lendsv, m, mm, i, ii, j, k, iscale;
    float anorm = 0.0f, p, g, r, c, s, f, b, rt1, rt2, tst, mul, t;

L10:
    if (l1 > n) goto L160;
    if (l1 > 1) e[l1 - 2] = 0.0f;
    if (l1 <= n - 1) {
        for (m = l1; m <= n - 1; m++) {
            tst = fabsf(e[m - 1]);
            if (tst == 0.0f) goto L30;
            {
                float thr = FMUL(FMUL(FSQRT(fabsf(d[m - 1])), FSQRT(fabsf(d[m]))), eps);
                if (tst <= thr) { e[m - 1] = 0.0f; goto L30; }
            }
        }
    }
    m = n;
L30:
    l = l1; lsv = l; lend = m; lendsv = lend; l1 = m + 1;
    if (lend == l) goto L10;

    anorm = fabsf(d[lend - 1]);
    for (i = l; i <= lend - 1; i++) {
        anorm = fmaxf(anorm, fabsf(d[i - 1]));
        anorm = fmaxf(anorm, fabsf(e[i - 1]));
    }
    iscale = 0;
    if (anorm == 0.0f) goto L10;
    if (anorm > ssfmax) {
        iscale = 1; mul = FDIV(ssfmax, anorm);
        for (i = l; i <= lend; i++) d[i - 1] = FMUL(d[i - 1], mul);
        for (i = l; i <= lend - 1; i++) e[i - 1] = FMUL(e[i - 1], mul);
    } else if (anorm < ssfmin) {
        iscale = 2; mul = FDIV(ssfmin, anorm);
        for (i = l; i <= lend; i++) d[i - 1] = FMUL(d[i - 1], mul);
        for (i = l; i <= lend - 1; i++) e[i - 1] = FMUL(e[i - 1], mul);
    }

    if (fabsf(d[lend - 1]) < fabsf(d[l - 1])) { lend = lsv; l = lendsv; }

    if (lend > l) {
L40:
        if (l != lend) {
            for (m = l; m <= lend - 1; m++) {
                tst = FMUL(e[m - 1], e[m - 1]);
                float rhs = FMAF(FMUL(eps2, fabsf(d[m - 1])), fabsf(d[m]), safmin);
                if (tst <= rhs) goto L60;
            }
        }
        m = lend;
L60:
        if (m < lend) e[m - 1] = 0.0f;
        p = d[l - 1];
        if (m == l) goto L80;
        if (m == l + 1) {
            slaev2f(d[l - 1], e[l - 1], d[l], &rt1, &rt2, &c, &s);
            for (i = 0; i < 3; i++) {
                t = z[i][l];
                z[i][l]     = FMAF(c, t, -FMUL(s, z[i][l - 1]));
                z[i][l - 1] = FMAF(s, t,  FMUL(c, z[i][l - 1]));
            }
            d[l - 1] = rt1; d[l] = rt2; e[l - 1] = 0.0f;
            l += 2;
            if (l <= lend) goto L40;
            goto L140;
        }
        if (jtot == nmaxit) goto L140;
        jtot++;
        g = FDIV(FSUB(d[l], p), FMUL(2.0f, e[l - 1]));
        r = slapy2f(g, 1.0f);
        g = FADD(FSUB(d[m - 1], p), FDIV(e[l - 1], FADD(g, f_sign(r, g))));
        s = 1.0f; c = 1.0f; p = 0.0f;
        for (i = m - 1; i >= l; i--) {
            f = FMUL(s, e[i - 1]); b = FMUL(c, e[i - 1]);
            slartgf(g, f, &c, &s, &r);
            if (i != m - 1) e[i] = r;
            g = FSUB(d[i], p);
            r = FMAF(FSUB(d[i - 1], g), s, FMUL(FMUL(2.0f, c), b));
            p = FMUL(s, r);
            d[i] = FADD(g, p);
            g = FMAF(c, r, -b);
            wc[i - l] = c;
            ws[i - l] = -s;
        }
        mm = m - l + 1;
        for (j = mm - 1; j >= 1; j--) {
            float cj = wc[j - 1], sj = ws[j - 1];
            for (i = 0; i < 3; i++) {
                t = z[i][l + j - 1];
                z[i][l + j - 1] = FMAF(cj, t, -FMUL(sj, z[i][l + j - 2]));
                z[i][l + j - 2] = FMAF(sj, t,  FMUL(cj, z[i][l + j - 2]));
            }
        }
        d[l - 1] = FSUB(d[l - 1], p);
        e[l - 1] = g;
        goto L40;
L80:
        d[l - 1] = p; l++;
        if (l <= lend) goto L40;
        goto L140;
    } else {
L90:
        if (l != lend) {
            for (m = l; m >= lend + 1; m--) {
                tst = FMUL(e[m - 2], e[m - 2]);
                float rhs = FMAF(FMUL(eps2, fabsf(d[m - 1])), fabsf(d[m - 2]), safmin);
                if (tst <= rhs) goto L110;
            }
        }
        m = lend;
L110:
        if (m > lend) e[m - 2] = 0.0f;
        p = d[l - 1];
        if (m == l) goto L130;
        if (m == l - 1) {
            slaev2f(d[l - 2], e[l - 2], d[l - 1], &rt1, &rt2, &c, &s);
            for (i = 0; i < 3; i++) {
                t = z[i][l - 1];
                z[i][l - 1] = FMAF(c, t, -FMUL(s, z[i][l - 2]));
                z[i][l - 2] = FMAF(s, t,  FMUL(c, z[i][l - 2]));
            }
            d[l - 2] = rt1; d[l - 1] = rt2; e[l - 2] = 0.0f;
            l -= 2;
            if (l >= lend) goto L90;
            goto L140;
        }
        if (jtot == nmaxit) goto L140;
        jtot++;
        g = FDIV(FSUB(d[l - 2], p), FMUL(2.0f, e[l - 2]));
        r = slapy2f(g, 1.0f);
        g = FADD(FSUB(d[m - 1], p), FDIV(e[l - 2], FADD(g, f_sign(r, g))));
        s = 1.0f; c = 1.0f; p = 0.0f;
        for (i = m; i <= l - 1; i++) {
            f = FMUL(s, e[i - 1]); b = FMUL(c, e[i - 1]);
            slartgf(g, f, &c, &s, &r);
            if (i != m) e[i - 2] = r;
            g = FSUB(d[i - 1], p);
            r = FMAF(FSUB(d[i], g), s, FMUL(FMUL(2.0f, c), b));
            p = FMUL(s, r);
            d[i - 1] = FADD(g, p);
            g = FMAF(c, r, -b);
            wc[i - m] = c;
            ws[i - m] = s;
        }
        mm = l - m + 1;
        for (j = 1; j <= mm - 1; j++) {
            float cj = wc[j - 1], sj = ws[j - 1];
            for (i = 0; i < 3; i++) {
                t = z[i][m + j - 1];
                z[i][m + j - 1] = FMAF(cj, t, -FMUL(sj, z[i][m + j - 2]));
                z[i][m + j - 2] = FMAF(sj, t,  FMUL(cj, z[i][m + j - 2]));
            }
        }
        d[l - 1] = FSUB(d[l - 1], p);
        e[l - 2] = g;
        goto L90;
L130:
        d[l - 1] = p; l--;
        if (l >= lend) goto L90;
        goto L140;
    }
L140:
    if (iscale == 1) {
        mul = FDIV(anorm, ssfmax);
        for (i = lsv; i <= lendsv; i++) d[i - 1] = FMUL(d[i - 1], mul);
        for (i = lsv; i <= lendsv - 1; i++) e[i - 1] = FMUL(e[i - 1], mul);
    } else if (iscale == 2) {
        mul = FDIV(anorm, ssfmin);
        for (i = lsv; i <= lendsv; i++) d[i - 1] = FMUL(d[i - 1], mul);
        for (i = lsv; i <= lendsv - 1; i++) e[i - 1] = FMUL(e[i - 1], mul);
    }
    if (jtot < nmaxit) goto L10;
    goto L190;
L160:
    for (ii = 2; ii <= n; ii++) {
        i = ii - 1; k = i; p = d[i - 1];
        for (j = ii; j <= n; j++) {
            if (d[j - 1] < p) { k = j; p = d[j - 1]; }
        }
        if (k != i) {
            d[k - 1] = d[i - 1]; d[i - 1] = p;
            for (int rr = 0; rr < 3; rr++) {
                t = z[rr][i - 1]; z[rr][i - 1] = z[rr][k - 1]; z[rr][k - 1] = t;
            }
        }
    }
L190:
    return;
}

// ---------------------------------------------------------------------------
// Kernel 1: pack (x,y,z,||p||^2) STRICT + cell id + count
// ---------------------------------------------------------------------------
__global__ void pack_kernel(const float* __restrict__ pts, int n) {
    int i = blockIdx.x * blockDim.x + threadIdx.x;
    if (i < n) {
        float x = pts[3 * i + 0];
        float y = pts[3 * i + 1];
        float z = pts[3 * i + 2];
        float sq = FADD(FADD(FMUL(x, x), FMUL(y, y)), FMUL(z, z));
        g_pts4[i] = make_float4(x, y, z, sq);
        int cx = min(GRID - 1, max(0, (int)(x * (float)GRID)));
        int cy = min(GRID - 1, max(0, (int)(y * (float)GRID)));
        int cz = min(GRID - 1, max(0, (int)(z * (float)GRID)));
        int cid = (cz * GRID + cy) * GRID + cx;
        g_cell[i] = cid;
        atomicAdd(&g_cnt[cid], 1);
    }
}

// ---------------------------------------------------------------------------
// Kernel 2: exclusive scan of 4096 cell counts
// ---------------------------------------------------------------------------
__global__ void scan_kernel() {
    __shared__ int sh[1024];
    int t = threadIdx.x;
    int c0 = g_cnt[4 * t + 0];
    int c1 = g_cnt[4 * t + 1];
    int c2 = g_cnt[4 * t + 2];
    int c3 = g_cnt[4 * t + 3];
    int sum = c0 + c1 + c2 + c3;
    sh[t] = sum;
    __syncthreads();
    for (int off = 1; off < 1024; off <<= 1) {
        int v = (t >= off) ? sh[t - off] : 0;
        __syncthreads();
        sh[t] += v;
        __syncthreads();
    }
    int excl = sh[t] - sum;
    g_off[4 * t + 0] = excl;
    g_off[4 * t + 1] = excl + c0;
    g_off[4 * t + 2] = excl + c0 + c1;
    g_off[4 * t + 3] = excl + c0 + c1 + c2;
    g_ptr[4 * t + 0] = excl;
    g_ptr[4 * t + 1] = excl + c0;
    g_ptr[4 * t + 2] = excl + c0 + c1;
    g_ptr[4 * t + 3] = excl + c0 + c1 + c2;
}

// ---------------------------------------------------------------------------
// Kernel 3: scatter points into cell-sorted order
// ---------------------------------------------------------------------------
__global__ void scatter_kernel(int n) {
    int i = blockIdx.x * blockDim.x + threadIdx.x;
    if (i < n) {
        int c = g_cell[i];
        int pos = atomicAdd(&g_ptr[c], 1);
        g_sorted[pos] = g_pts4[i];
        g_sidx[pos] = i;
    }
}

// ---------------------------------------------------------------------------
// Kernel 4 (8 lanes/query): cooperative grid 5-NN, u64 keys, span scan.
// Leader writes 5 neighbor indices to g_nbr (indexed by sorted slot).
// ---------------------------------------------------------------------------
__global__ void __launch_bounds__(256, 1)
knn_kernel(int n) {
    int T = blockIdx.x * blockDim.x + threadIdx.x;
    int qid = T >> 3;
    int lg = T & 7;
    if (qid >= n) return;
    unsigned gmask = 0xFFu << (8 * ((threadIdx.x & 31) >> 3));

    float4 q = g_sorted[qid];

    int cx = min(GRID - 1, max(0, (int)(q.x * (float)GRID)));
    int cy = min(GRID - 1, max(0, (int)(q.y * (float)GRID)));
    int cz = min(GRID - 1, max(0, (int)(q.z * (float)GRID)));

    u64 w0, w1, w2, w3, w4;

    for (int Rmax = 1; Rmax <= GRID - 1; Rmax++) {
        u64 l0 = ~0ULL, l1 = ~0ULL, l2 = ~0ULL, l3 = ~0ULL, l4 = ~0ULL;

        int z0 = max(cz - Rmax, 0), z1 = min(cz + Rmax, GRID - 1);
        int y0 = max(cy - Rmax, 0), y1 = min(cy + Rmax, GRID - 1);
        int x0 = max(cx - Rmax, 0), x1 = min(cx + Rmax, GRID - 1);
        for (int zz = z0; zz <= z1; zz++)
            for (int yy = y0; yy <= y1; yy++) {
                int rowbase = (zz * GRID + yy) * GRID;
                int a = g_off[rowbase + x0];
                int b = g_off[rowbase + x1] + g_cnt[rowbase + x1];
                for (int t = a + lg; t < b; t += 8) {
                    float4 p = g_sorted[t];
                    int idx = g_sidx[t];
                    float dot = FADD(FADD(FMUL(q.x, p.x), FMUL(q.y, p.y)), FMUL(q.z, p.z));
                    float d2 = FSUB(FADD(q.w, p.w), FMUL(2.0f, dot));
                    u64 key = ((u64)f2ord(d2) << 32) | (u32)idx;
                    if (key < l4) {
                        if (key < l3) {
                            l4 = l3;
                            if (key < l2) {
                                l3 = l2;
                                if (key < l1) {
                                    l2 = l1;
                                    if (key < l0) { l1 = l0; l0 = key; }
                                    else l1 = key;
                                } else l2 = key;
                            } else l3 = key;
                        } else l4 = key;
                    }
                }
            }

        #pragma unroll
        for (int r = 0; r < 5; r++) {
            u64 c = l0;
            #pragma unroll
            for (int off = 1; off < 8; off <<= 1) {
                u64 o = __shfl_xor_sync(gmask, c, off);
                if (o < c) c = o;
            }
            if (r == 0) w0 = c;
            else if (r == 1) w1 = c;
            else if (r == 2) w2 = c;
            else if (r == 3) w3 = c;
            else w4 = c;
            if (l0 == c) { l0 = l1; l1 = l2; l2 = l3; l3 = l4; l4 = ~0ULL; }
        }

        float bd4 = ord2f((u32)(w4 >> 32));
        float guard = (float)Rmax * CELLH;
        if (bd4 < guard * guard - 1e-5f) break;
    }

    if (lg == 0) {
        int* nb = g_nbr + qid * KNBR;
        nb[0] = (int)(u32)w0;
        nb[1] = (int)(u32)w1;
        nb[2] = (int)(u32)w2;
        nb[3] = (int)(u32)w3;
        nb[4] = (int)(u32)w4;
    }
}

// ---------------------------------------------------------------------------
// Kernel 5: thread-per-point LRF (FROZEN bit recipe), sorted order.
// ---------------------------------------------------------------------------
__global__ void __launch_bounds__(256, 1)
lrf_kernel(float* __restrict__ out, int n) {
    int s = blockIdx.x * blockDim.x + threadIdx.x;
    if (s >= n) return;
    float4 q = g_sorted[s];
    int qi = g_sidx[s];

    float dx[KNBR], dy[KNBR], dz[KNBR];
    #pragma unroll
    for (int k = 0; k < KNBR; k++) {
        float4 p = g_pts4[g_nbr[s * KNBR + k]];
        dx[k] = FSUB(p.x, q.x);
        dy[k] = FSUB(p.y, q.y);
        dz[k] = FSUB(p.z, q.z);
    }
    float sxm = FADD(FADD(FADD(FADD(dx[0], dx[1]), dx[2]), dx[3]), dx[4]);
    float sym = FADD(FADD(FADD(FADD(dy[0], dy[1]), dy[2]), dy[3]), dy[4]);
    float szm = FADD(FADD(FADD(FADD(dz[0], dz[1]), dz[2]), dz[3]), dz[4]);
    float mx = FDIV(sxm, 5.0f);
    float my = FDIV(sym, 5.0f);
    float mz = FDIV(szm, 5.0f);

    float cxa[KNBR], cya[KNBR], cza[KNBR];
    #pragma unroll
    for (int k = 0; k < KNBR; k++) {
        cxa[k] = FSUB(dx[k], mx);
        cya[k] = FSUB(dy[k], my);
        cza[k] = FSUB(dz[k], mz);
    }
    float c00 = 0.f, c10 = 0.f, c20 = 0.f, c11 = 0.f, c21 = 0.f, c22 = 0.f;
    #pragma unroll
    for (int k = 0; k < KNBR; k++) {
        c00 = FMAF(cxa[k], cxa[k], c00);
        c10 = FMAF(cya[k], cxa[k], c10);
        c20 = FMAF(cza[k], cxa[k], c20);
        c11 = FMAF(cya[k], cya[k], c11);
        c21 = FMAF(cza[k], cya[k], c21);
        c22 = FMAF(cza[k], cza[k], c22);
    }
    c00 = FDIV(c00, 5.0f); c10 = FDIV(c10, 5.0f); c20 = FDIV(c20, 5.0f);
    c11 = FDIV(c11, 5.0f); c21 = FDIV(c21, 5.0f); c22 = FDIV(c22, 5.0f);

    // ---- ssytd2 'L', n=3 ----
    float e0, e1s, tau = 0.0f, v2 = 0.0f;
    float a11 = c11, a21 = c21, a22 = c22;
    {
        float alpha = c10;
        float xnorm = FSQRT(FMUL(c20, c20));
        if (xnorm == 0.0f) {
            tau = 0.0f;
            e0 = alpha;
        } else {
            float beta = -f_sign(slapy2f(alpha, xnorm), alpha);
            tau = FDIV(FSUB(beta, alpha), beta);
            v2  = FMUL(c20, FDIV(1.0f, FSUB(alpha, beta)));
            e0  = beta;
            float y1 = FMAF(tau, FMUL(a21, v2), FMUL(tau, a11));
            float y2 = FMAF(FMUL(tau, v2), a22, FMUL(tau, a21));
            float sdot = FMAF(y2, v2, y1);
            float ac = FMUL(FMUL(-0.5f, tau), sdot);
            y1 = FMAF(ac, 1.0f, y1);
            y2 = FMAF(ac, v2, y2);
            a11 = FMAF(y1, -1.0f, FMAF(1.0f, -y1, a11));
            a21 = FMAF(y2, -1.0f, FMAF(v2,  -y1, a21));
            a22 = FMAF(y2, -v2,   FMAF(v2,  -y2, a22));
        }
        e1s = a21;
    }

    float d[3] = { c00, a11, a22 };
    float e[2] = { e0, e1s };
    float z[3][3] = { {1.f,0.f,0.f}, {0.f,1.f,0.f}, {0.f,0.f,1.f} };

    steqr3(d, e, z);

    if (tau != 0.0f) {
        #pragma unroll
        for (int jc = 0; jc < 3; jc++) {
            float w = FMAF(z[2][jc], v2, z[1][jc]);
            float tneg = FMUL(-tau, w);
            z[1][jc] = FMAF(1.0f, tneg, z[1][jc]);
            z[2][jc] = FMAF(v2,  tneg, z[2][jc]);
        }
    }

    float xr0 = z[2][0], xr1 = z[2][1], xr2 = z[2][2];
    float zr0 = z[0][0], zr1 = z[0][1], zr2 = z[0][2];

    int cx_cnt = 0, cz_cnt = 0;
    #pragma unroll
    for (int k = 0; k < KNBR; k++) {
        float wx = FSUB(dx[k], q.x);
        float wy = FSUB(dy[k], q.y);
        float wz = FSUB(dz[k], q.z);
        float dotx = FMAF(wz, xr2, FMAF(wy, xr1, FMUL(wx, xr0)));
        float dotz = FMAF(wz, zr2, FMAF(wy, zr1, FMUL(wx, zr0)));
        if (dotx >= -EPSV) cx_cnt++;
        if (dotz >= -EPSV) cz_cnt++;
    }
    float sx = (2 * cx_cnt >= KNBR) ? 1.0f : -1.0f;
    float sz = (2 * cz_cnt >= KNBR) ? 1.0f : -1.0f;

    float xa0 = FMUL(xr0, sx), xa1 = FMUL(xr1, sx), xa2 = FMUL(xr2, sx);
    float za0 = FMUL(zr0, sz), za1 = FMUL(zr1, sz), za2 = FMUL(zr2, sz);
    float ya0 = FSUB(FMUL(za1, xa2), FMUL(za2, xa1));
    float ya1 = FSUB(FMUL(za2, xa0), FMUL(za0, xa2));
    float ya2 = FSUB(FMUL(za0, xa1), FMUL(za1, xa0));

    float* o = out + (size_t)qi * 9;
    o[0] = xa0; o[1] = xa1; o[2] = xa2;
    o[3] = ya0; o[4] = ya1; o[5] = ya2;
    o[6] = za0; o[7] = za1; o[8] = za2;
}

// ---------------------------------------------------------------------------
extern "C" void kernel_launch(void* const* d_in, const int* in_sizes, int n_in,
                              void* d_out, int out_size) {
    const float* pts = (const float*)d_in[0];
    float* out = (float*)d_out;
    int n = in_sizes[0] / 3;
    if (n > NPTS_MAX) n = NPTS_MAX;

    void* cnt_ptr = nullptr;
    cudaGetSymbolAddress(&cnt_ptr, g_cnt);
    cudaMemsetAsync(cnt_ptr, 0, NCELL * sizeof(int));

    pack_kernel<<<(n + 255) / 256, 256>>>(pts, n);
    scan_kernel<<<1, 1024>>>();
    scatter_kernel<<<(n + 255) / 256, 256>>>(n);
    int threads = n * 8;
    knn_kernel<<<(threads + 255) / 256, 256>>>(n);
    lrf_kernel<<<(n + 255) / 256, 256>>>(out, n);
}